// round 1
// baseline (speedup 1.0000x reference)
#include <cuda_runtime.h>
#include <math.h>

// Problem constants
static const int cB = 8;
static const int cS = 2048;
static const int cD = 512;
static const int cL = 6;
static const int cF = 2048;   // 4*D
static const int cM = cB * cS; // 16384 rows

// ---------------------------------------------------------------------------
// Scratch (static device allocations; no cudaMalloc allowed)
// ---------------------------------------------------------------------------
__device__ float g_x  [cB * cS * cD];   // activations
__device__ float g_xn [cB * cS * cD];   // layernormed activations
__device__ float g_q  [cB * cS * cD];
__device__ float g_k  [cB * cS * cD];
__device__ float g_v  [cB * cS * cD];
__device__ float g_ao [cB * cS * cD];   // attention output
__device__ float g_att[(long long)cB * cS * cS]; // attention scores/probs
__device__ float g_h  [(long long)cM * cF];      // FFN hidden
__device__ float g_tab[cS];             // bias table per layer

// ---------------------------------------------------------------------------
// Encoder: x = z*enc_w[:,0] + c*enc_w[:,1] + enc_b + posenc
// ---------------------------------------------------------------------------
__global__ void enc_kernel(const float* __restrict__ z, const float* __restrict__ c,
                           const float* __restrict__ ew, const float* __restrict__ eb,
                           float* __restrict__ x)
{
    long long idx = (long long)blockIdx.x * blockDim.x + threadIdx.x;
    if (idx >= (long long)cB * cS * cD) return;
    int d = (int)(idx & (cD - 1));
    long long bs = idx >> 9;            // cD = 512 = 2^9
    int s = (int)(bs & (cS - 1));
    // match jax: div = exp(float(2*half) * float(-log(10000)/512))
    const float factor = -1.7988946039015984e-2f;
    float div = expf((float)(2 * (d >> 1)) * factor);
    float ang = (float)s * div;
    float pe = (d & 1) ? cosf(ang) : sinf(ang);
    x[idx] = z[bs] * ew[2 * d] + c[bs] * ew[2 * d + 1] + eb[d] + pe;
}

// ---------------------------------------------------------------------------
// Attention bias table: tab[t] = b0*cos(2*pi*t/24) + b1*cos(2*pi*t/720)
// ---------------------------------------------------------------------------
__global__ void btab_kernel(const float* __restrict__ beta, int l, float* __restrict__ tab)
{
    int t = blockIdx.x * blockDim.x + threadIdx.x;
    if (t < cS) {
        const float TWO_PI = 6.283185307179586476925f;
        float a0 = TWO_PI * (float)t / 24.0f;
        float a1 = TWO_PI * (float)t / 720.0f;
        tab[t] = beta[2 * l] * cosf(a0) + beta[2 * l + 1] * cosf(a1);
    }
}

// ---------------------------------------------------------------------------
// LayerNorm over D=512: out = (x(+res) - mean) * rsqrt(var+eps) * w + b
// one block (128 threads) per row, 4 elems/thread (float4)
// ---------------------------------------------------------------------------
__global__ __launch_bounds__(128) void ln_kernel(
    const float* __restrict__ x, const float* __restrict__ res,
    const float* __restrict__ w, const float* __restrict__ b,
    float* __restrict__ out)
{
    long long off = (long long)blockIdx.x * cD + threadIdx.x * 4;
    float4 v = *(const float4*)(x + off);
    if (res) {
        float4 r = *(const float4*)(res + off);
        v.x += r.x; v.y += r.y; v.z += r.z; v.w += r.w;
    }
    int lane = threadIdx.x & 31, warp = threadIdx.x >> 5;
    __shared__ float red1[4];
    __shared__ float red2[4];

    float s = v.x + v.y + v.z + v.w;
    #pragma unroll
    for (int o = 16; o; o >>= 1) s += __shfl_xor_sync(0xffffffffu, s, o);
    if (lane == 0) red1[warp] = s;
    __syncthreads();
    float mean = (red1[0] + red1[1] + red1[2] + red1[3]) * (1.0f / 512.0f);

    float d0 = v.x - mean, d1 = v.y - mean, d2 = v.z - mean, d3 = v.w - mean;
    float q = d0 * d0 + d1 * d1 + d2 * d2 + d3 * d3;
    #pragma unroll
    for (int o = 16; o; o >>= 1) q += __shfl_xor_sync(0xffffffffu, q, o);
    if (lane == 0) red2[warp] = q;
    __syncthreads();
    float var = (red2[0] + red2[1] + red2[2] + red2[3]) * (1.0f / 512.0f);
    float rs = rsqrtf(var + 1e-5f);

    float4 wv = *(const float4*)(w + threadIdx.x * 4);
    float4 bv = *(const float4*)(b + threadIdx.x * 4);
    float4 o4;
    o4.x = d0 * rs * wv.x + bv.x;
    o4.y = d1 * rs * wv.y + bv.y;
    o4.z = d2 * rs * wv.z + bv.z;
    o4.w = d3 * rs * wv.w + bv.w;
    *(float4*)(out + off) = o4;
}

// ---------------------------------------------------------------------------
// Softmax with distance bias, row length S=2048, row cached in smem
// grid (S, B), block 256
// ---------------------------------------------------------------------------
__global__ __launch_bounds__(256) void softmax_kernel(float* __restrict__ att,
                                                      const float* __restrict__ tab)
{
    __shared__ float buf[cS];
    __shared__ float red[8];
    int i = blockIdx.x, b = blockIdx.y;
    float* row = att + ((long long)b * cS + i) * cS;
    int tid = threadIdx.x;

    float mx = -3.4e38f;
    for (int j = tid; j < cS; j += 256) {
        int d = i - j; if (d < 0) d = -d;
        float vv = row[j] + tab[d];
        buf[j] = vv;
        mx = fmaxf(mx, vv);
    }
    #pragma unroll
    for (int o = 16; o; o >>= 1) mx = fmaxf(mx, __shfl_xor_sync(0xffffffffu, mx, o));
    if ((tid & 31) == 0) red[tid >> 5] = mx;
    __syncthreads();
    float m = red[0];
    #pragma unroll
    for (int w2 = 1; w2 < 8; w2++) m = fmaxf(m, red[w2]);
    __syncthreads();

    float sum = 0.0f;
    for (int j = tid; j < cS; j += 256) {
        float e = expf(buf[j] - m);
        buf[j] = e;
        sum += e;
    }
    #pragma unroll
    for (int o = 16; o; o >>= 1) sum += __shfl_xor_sync(0xffffffffu, sum, o);
    if ((tid & 31) == 0) red[tid >> 5] = sum;
    __syncthreads();
    float tot = 0.0f;
    #pragma unroll
    for (int w2 = 0; w2 < 8; w2++) tot += red[w2];
    float inv = 1.0f / tot;
    for (int j = tid; j < cS; j += 256) row[j] = buf[j] * inv;
}

// ---------------------------------------------------------------------------
// Generic batched GEMM: C = alpha * A @ op(B) (+bias) (+src) (relu)
//   A: [M,K] row-major, op(B) = B^T if TB (B is [N,K]) else B ([K,N])
//   64x64x16 tiles, 256 threads, 4x4 per thread. All dims divide tile sizes.
// ---------------------------------------------------------------------------
template<bool TB, bool RELU, bool ADDSRC>
__global__ __launch_bounds__(256) void gemm_kernel(
    const float* __restrict__ A, const float* __restrict__ B,
    const float* __restrict__ bias, const float* __restrict__ src,
    float* __restrict__ C, int M, int N, int K,
    long long bsA, long long bsB, long long bsC, float alpha)
{
    A += (long long)blockIdx.z * bsA;
    B += (long long)blockIdx.z * bsB;
    C += (long long)blockIdx.z * bsC;
    const float* srcp = ADDSRC ? (src + (long long)blockIdx.z * bsC) : (const float*)0;

    __shared__ float As[16][64];
    __shared__ float Bs[16][64];

    const int tid = threadIdx.x;
    const int tx = tid & 15, ty = tid >> 4;
    const int rowBase = blockIdx.y * 64, colBase = blockIdx.x * 64;

    const int lRow = tid >> 2;          // 0..63
    const int lCol = (tid & 3) << 2;    // 0,4,8,12
    const int nRow = tid >> 4;          // 0..15 (k)  (NN path)
    const int nCol = (tid & 15) << 2;   // 0..60      (NN path)

    float acc[4][4] = {};

    for (int k0 = 0; k0 < K; k0 += 16) {
        float4 av = *(const float4*)(A + (long long)(rowBase + lRow) * K + k0 + lCol);
        As[lCol + 0][lRow] = av.x; As[lCol + 1][lRow] = av.y;
        As[lCol + 2][lRow] = av.z; As[lCol + 3][lRow] = av.w;
        if (TB) {
            float4 bv = *(const float4*)(B + (long long)(colBase + lRow) * K + k0 + lCol);
            Bs[lCol + 0][lRow] = bv.x; Bs[lCol + 1][lRow] = bv.y;
            Bs[lCol + 2][lRow] = bv.z; Bs[lCol + 3][lRow] = bv.w;
        } else {
            float4 bv = *(const float4*)(B + (long long)(k0 + nRow) * N + colBase + nCol);
            *(float4*)&Bs[nRow][nCol] = bv;
        }
        __syncthreads();
        #pragma unroll
        for (int kk = 0; kk < 16; kk++) {
            float4 a4 = *(const float4*)&As[kk][ty << 2];
            float4 b4 = *(const float4*)&Bs[kk][tx << 2];
            float a[4] = {a4.x, a4.y, a4.z, a4.w};
            float b[4] = {b4.x, b4.y, b4.z, b4.w};
            #pragma unroll
            for (int i = 0; i < 4; i++)
                #pragma unroll
                for (int j = 0; j < 4; j++)
                    acc[i][j] += a[i] * b[j];
        }
        __syncthreads();
    }

    #pragma unroll
    for (int i = 0; i < 4; i++) {
        int r = rowBase + (ty << 2) + i;
        #pragma unroll
        for (int j = 0; j < 4; j++) {
            int cidx = colBase + (tx << 2) + j;
            float vv = alpha * acc[i][j];
            if (bias) vv += bias[cidx];
            if (ADDSRC) vv += srcp[(long long)r * N + cidx];
            if (RELU) vv = fmaxf(vv, 0.0f);
            C[(long long)r * N + cidx] = vv;
        }
    }
}

// ---------------------------------------------------------------------------
// Output head: out[row] = dot(x[row,:], out_w) + out_b   (ODIM = 1)
// one warp per row
// ---------------------------------------------------------------------------
__global__ __launch_bounds__(256) void out_kernel(
    const float* __restrict__ x, const float* __restrict__ ow,
    const float* __restrict__ ob, float* __restrict__ out)
{
    int warp = threadIdx.x >> 5, lane = threadIdx.x & 31;
    long long row = (long long)blockIdx.x * 8 + warp;
    const float* xr = x + row * cD;
    float s = 0.0f;
    #pragma unroll
    for (int j = lane; j < cD; j += 32) s += xr[j] * ow[j];
    #pragma unroll
    for (int o = 16; o; o >>= 1) s += __shfl_xor_sync(0xffffffffu, s, o);
    if (lane == 0) out[row] = s + ob[0];
}

// ---------------------------------------------------------------------------
// Launch
// ---------------------------------------------------------------------------
extern "C" void kernel_launch(void* const* d_in, const int* in_sizes, int n_in,
                              void* d_out, int out_size)
{
    (void)in_sizes; (void)n_in; (void)out_size;
    const float* z    = (const float*)d_in[0];
    const float* c    = (const float*)d_in[1];
    const float* encw = (const float*)d_in[2];
    const float* encb = (const float*)d_in[3];
    const float* beta = (const float*)d_in[4];
    const float* wq   = (const float*)d_in[5];
    const float* bq   = (const float*)d_in[6];
    const float* wk   = (const float*)d_in[7];
    const float* bk   = (const float*)d_in[8];
    const float* wv   = (const float*)d_in[9];
    const float* bv   = (const float*)d_in[10];
    const float* ln1w = (const float*)d_in[11];
    const float* ln1b = (const float*)d_in[12];
    const float* ln2w = (const float*)d_in[13];
    const float* ln2b = (const float*)d_in[14];
    const float* f1w  = (const float*)d_in[15];
    const float* f1b  = (const float*)d_in[16];
    const float* f2w  = (const float*)d_in[17];
    const float* f2b  = (const float*)d_in[18];
    const float* ow   = (const float*)d_in[19];
    const float* ob   = (const float*)d_in[20];

    float *x, *xn, *q, *k, *v, *ao, *att, *h, *tab;
    cudaGetSymbolAddress((void**)&x,   g_x);
    cudaGetSymbolAddress((void**)&xn,  g_xn);
    cudaGetSymbolAddress((void**)&q,   g_q);
    cudaGetSymbolAddress((void**)&k,   g_k);
    cudaGetSymbolAddress((void**)&v,   g_v);
    cudaGetSymbolAddress((void**)&ao,  g_ao);
    cudaGetSymbolAddress((void**)&att, g_att);
    cudaGetSymbolAddress((void**)&h,   g_h);
    cudaGetSymbolAddress((void**)&tab, g_tab);

    const long long SD = (long long)cS * cD;
    const long long SSq = (long long)cS * cS;
    const float inv_sqrt_d = 0.044194173824159216f; // 1/sqrt(512)

    enc_kernel<<<(cB * cS * cD + 255) / 256, 256>>>(z, c, encw, encb, x);

    for (int l = 0; l < cL; l++) {
        const float* wql = wq + (long long)l * cD * cD;
        const float* wkl = wk + (long long)l * cD * cD;
        const float* wvl = wv + (long long)l * cD * cD;

        // pre-norm (ln1)
        ln_kernel<<<cM, 128>>>(x, (const float*)0, ln1w + l * cD, ln1b + l * cD, xn);

        dim3 gQKV(cD / 64, cM / 64, 1);
        gemm_kernel<true, false, false><<<gQKV, 256>>>(xn, wql, bq + l * cD, (const float*)0, q,
                                                       cM, cD, cD, 0, 0, 0, 1.0f);
        gemm_kernel<true, false, false><<<gQKV, 256>>>(xn, wkl, bk + l * cD, (const float*)0, k,
                                                       cM, cD, cD, 0, 0, 0, 1.0f);
        gemm_kernel<true, false, false><<<gQKV, 256>>>(xn, wvl, bv + l * cD, (const float*)0, v,
                                                       cM, cD, cD, 0, 0, 0, 1.0f);

        btab_kernel<<<cS / 256, 256>>>(beta, l, tab);

        // attn = Q @ K^T / sqrt(d)   per batch
        dim3 gS(cS / 64, cS / 64, cB);
        gemm_kernel<true, false, false><<<gS, 256>>>(q, k, (const float*)0, (const float*)0, att,
                                                     cS, cS, cD, SD, SD, SSq, inv_sqrt_d);

        softmax_kernel<<<dim3(cS, cB), 256>>>(att, tab);

        // att_out = probs @ V   per batch (NN)
        dim3 gV(cD / 64, cS / 64, cB);
        gemm_kernel<false, false, false><<<gV, 256>>>(att, v, (const float*)0, (const float*)0, ao,
                                                      cS, cD, cS, SSq, SD, SD, 1.0f);

        // x = LN(x + att_out) with ln1 params (in-place)
        ln_kernel<<<cM, 128>>>(x, ao, ln1w + l * cD, ln1b + l * cD, x);
        // xn = LN(x) with ln2 params
        ln_kernel<<<cM, 128>>>(x, (const float*)0, ln2w + l * cD, ln2b + l * cD, xn);

        // h = relu(xn @ ff1^T + b1)
        dim3 g1(cF / 64, cM / 64, 1);
        gemm_kernel<true, true, false><<<g1, 256>>>(xn, f1w + (long long)l * cF * cD, f1b + l * cF,
                                                    (const float*)0, h, cM, cF, cD, 0, 0, 0, 1.0f);
        // x = x + h @ ff2^T + b2  (in-place residual)
        dim3 g2(cD / 64, cM / 64, 1);
        gemm_kernel<true, false, true><<<g2, 256>>>(h, f2w + (long long)l * cD * cF, f2b + l * cD,
                                                    x, x, cM, cD, cF, 0, 0, 0, 1.0f);
    }

    out_kernel<<<cM / 8, 256>>>(x, ow, ob, (float*)d_out);
}

// round 3
// speedup vs baseline: 1.2506x; 1.2506x over previous
#include <cuda_runtime.h>
#include <math.h>

// Problem constants
static const int cB = 8;
static const int cS = 2048;
static const int cD = 512;
static const int cL = 6;
static const int cF = 2048;   // 4*D
static const int cM = cB * cS; // 16384 rows

// ---------------------------------------------------------------------------
// Scratch (static device allocations; no cudaMalloc allowed)
// ---------------------------------------------------------------------------
__device__ float g_x  [cB * cS * cD];
__device__ float g_xn [cB * cS * cD];
__device__ float g_q  [cB * cS * cD];
__device__ float g_k  [cB * cS * cD];
__device__ float g_v  [cB * cS * cD];
__device__ float g_ao [cB * cS * cD];
__device__ float g_att[(long long)cB * cS * cS];
__device__ float g_h  [(long long)cM * cF];
__device__ float g_tab[cS];

// ---------------------------------------------------------------------------
// Encoder: x = z*enc_w[:,0] + c*enc_w[:,1] + enc_b + posenc
// ---------------------------------------------------------------------------
__global__ void enc_kernel(const float* __restrict__ z, const float* __restrict__ c,
                           const float* __restrict__ ew, const float* __restrict__ eb,
                           float* __restrict__ x)
{
    long long idx = (long long)blockIdx.x * blockDim.x + threadIdx.x;
    if (idx >= (long long)cB * cS * cD) return;
    int d = (int)(idx & (cD - 1));
    long long bs = idx >> 9;
    int s = (int)(bs & (cS - 1));
    const float factor = -1.7988946039015984e-2f;
    float div = expf((float)(2 * (d >> 1)) * factor);
    float ang = (float)s * div;
    float pe = (d & 1) ? cosf(ang) : sinf(ang);
    x[idx] = z[bs] * ew[2 * d] + c[bs] * ew[2 * d + 1] + eb[d] + pe;
}

// ---------------------------------------------------------------------------
// Attention bias table
// ---------------------------------------------------------------------------
__global__ void btab_kernel(const float* __restrict__ beta, int l, float* __restrict__ tab)
{
    int t = blockIdx.x * blockDim.x + threadIdx.x;
    if (t < cS) {
        const float TWO_PI = 6.283185307179586476925f;
        float a0 = TWO_PI * (float)t / 24.0f;
        float a1 = TWO_PI * (float)t / 720.0f;
        tab[t] = beta[2 * l] * cosf(a0) + beta[2 * l + 1] * cosf(a1);
    }
}

// ---------------------------------------------------------------------------
// LayerNorm over D=512
// ---------------------------------------------------------------------------
__global__ __launch_bounds__(128) void ln_kernel(
    const float* __restrict__ x, const float* __restrict__ res,
    const float* __restrict__ w, const float* __restrict__ b,
    float* __restrict__ out)
{
    long long off = (long long)blockIdx.x * cD + threadIdx.x * 4;
    float4 v = *(const float4*)(x + off);
    if (res) {
        float4 r = *(const float4*)(res + off);
        v.x += r.x; v.y += r.y; v.z += r.z; v.w += r.w;
    }
    int lane = threadIdx.x & 31, warp = threadIdx.x >> 5;
    __shared__ float red1[4];
    __shared__ float red2[4];

    float s = v.x + v.y + v.z + v.w;
    #pragma unroll
    for (int o = 16; o; o >>= 1) s += __shfl_xor_sync(0xffffffffu, s, o);
    if (lane == 0) red1[warp] = s;
    __syncthreads();
    float mean = (red1[0] + red1[1] + red1[2] + red1[3]) * (1.0f / 512.0f);

    float d0 = v.x - mean, d1 = v.y - mean, d2 = v.z - mean, d3 = v.w - mean;
    float q = d0 * d0 + d1 * d1 + d2 * d2 + d3 * d3;
    #pragma unroll
    for (int o = 16; o; o >>= 1) q += __shfl_xor_sync(0xffffffffu, q, o);
    if (lane == 0) red2[warp] = q;
    __syncthreads();
    float var = (red2[0] + red2[1] + red2[2] + red2[3]) * (1.0f / 512.0f);
    float rs = rsqrtf(var + 1e-5f);

    float4 wv = *(const float4*)(w + threadIdx.x * 4);
    float4 bv = *(const float4*)(b + threadIdx.x * 4);
    float4 o4;
    o4.x = d0 * rs * wv.x + bv.x;
    o4.y = d1 * rs * wv.y + bv.y;
    o4.z = d2 * rs * wv.z + bv.z;
    o4.w = d3 * rs * wv.w + bv.w;
    *(float4*)(out + off) = o4;
}

// ---------------------------------------------------------------------------
// Softmax with distance bias
// ---------------------------------------------------------------------------
__global__ __launch_bounds__(256) void softmax_kernel(float* __restrict__ att,
                                                      const float* __restrict__ tab)
{
    __shared__ float buf[cS];
    __shared__ float red[8];
    int i = blockIdx.x, b = blockIdx.y;
    float* row = att + ((long long)b * cS + i) * cS;
    int tid = threadIdx.x;

    float mx = -3.4e38f;
    for (int j = tid; j < cS; j += 256) {
        int d = i - j; if (d < 0) d = -d;
        float vv = row[j] + tab[d];
        buf[j] = vv;
        mx = fmaxf(mx, vv);
    }
    #pragma unroll
    for (int o = 16; o; o >>= 1) mx = fmaxf(mx, __shfl_xor_sync(0xffffffffu, mx, o));
    if ((tid & 31) == 0) red[tid >> 5] = mx;
    __syncthreads();
    float m = red[0];
    #pragma unroll
    for (int w2 = 1; w2 < 8; w2++) m = fmaxf(m, red[w2]);
    __syncthreads();

    float sum = 0.0f;
    for (int j = tid; j < cS; j += 256) {
        float e = expf(buf[j] - m);
        buf[j] = e;
        sum += e;
    }
    #pragma unroll
    for (int o = 16; o; o >>= 1) sum += __shfl_xor_sync(0xffffffffu, sum, o);
    if ((tid & 31) == 0) red[tid >> 5] = sum;
    __syncthreads();
    float tot = 0.0f;
    #pragma unroll
    for (int w2 = 0; w2 < 8; w2++) tot += red[w2];
    float inv = 1.0f / tot;
    for (int j = tid; j < cS; j += 256) row[j] = buf[j] * inv;
}

// ---------------------------------------------------------------------------
// Batched GEMM: C = alpha * A @ op(B) (+bias) (+src) (relu)
//   A: [M,K] row-major, op(B)=B^T if TB (B is [N,K]) else B ([K,N])
//   128x128x8 tiles, 256 threads, 8x8 per thread, double-buffered smem.
//   All dims divide tile sizes (M,N multiples of 128; K multiple of 8).
// ---------------------------------------------------------------------------
template<bool TB, bool RELU, bool ADDSRC>
__global__ __launch_bounds__(256) void gemm128(
    const float* __restrict__ A, const float* __restrict__ B,
    const float* __restrict__ bias, const float* __restrict__ src,
    float* __restrict__ C, int M, int N, int K,
    long long bsA, long long bsB, long long bsC, float alpha)
{
    A += (long long)blockIdx.z * bsA;
    B += (long long)blockIdx.z * bsB;
    C += (long long)blockIdx.z * bsC;
    const float* srcp = ADDSRC ? (src + (long long)blockIdx.z * bsC) : (const float*)0;

    __shared__ float As[2][8][128];
    __shared__ float Bs[2][8][128];

    const int tid = threadIdx.x;
    const int rowBase = blockIdx.y * 128, colBase = blockIdx.x * 128;

    // loaders
    const int aRow = tid >> 1;           // 0..127
    const int aK   = (tid & 1) << 2;     // 0 or 4
    const int nK   = tid >> 5;           // 0..7   (NN path)
    const int nC   = (tid & 31) << 2;    // 0..124 (NN path)

    const float* Aptr  = A + (long long)(rowBase + aRow) * K + aK;
    const float* BptrT = B + (long long)(colBase + aRow) * K + aK;
    const float* BptrN = B + (long long)nK * N + colBase + nC;

    // initial tile -> buffer 0
    {
        float4 av = *(const float4*)Aptr;
        As[0][aK + 0][aRow] = av.x; As[0][aK + 1][aRow] = av.y;
        As[0][aK + 2][aRow] = av.z; As[0][aK + 3][aRow] = av.w;
        if (TB) {
            float4 bv = *(const float4*)BptrT;
            Bs[0][aK + 0][aRow] = bv.x; Bs[0][aK + 1][aRow] = bv.y;
            Bs[0][aK + 2][aRow] = bv.z; Bs[0][aK + 3][aRow] = bv.w;
        } else {
            float4 bv = *(const float4*)BptrN;
            *(float4*)&Bs[0][nK][nC] = bv;
        }
    }
    __syncthreads();

    const int ty = (tid >> 4) << 3;   // 0..120 step 8 (row)
    const int tx = (tid & 15) << 3;   // 0..120 step 8 (col)

    float acc[8][8] = {};
    int buf = 0;

    for (int k0 = 0; k0 < K; k0 += 8) {
        const bool last = (k0 + 8 >= K);
        float4 aReg, bReg;
        if (!last) {
            aReg = *(const float4*)(Aptr + k0 + 8);
            bReg = TB ? *(const float4*)(BptrT + k0 + 8)
                      : *(const float4*)(BptrN + (long long)(k0 + 8) * N);
        }

        #pragma unroll
        for (int kk = 0; kk < 8; kk++) {
            float4 a0 = *(const float4*)&As[buf][kk][ty];
            float4 a1 = *(const float4*)&As[buf][kk][ty + 4];
            float4 b0 = *(const float4*)&Bs[buf][kk][tx];
            float4 b1 = *(const float4*)&Bs[buf][kk][tx + 4];
            float a[8] = {a0.x, a0.y, a0.z, a0.w, a1.x, a1.y, a1.z, a1.w};
            float b[8] = {b0.x, b0.y, b0.z, b0.w, b1.x, b1.y, b1.z, b1.w};
            #pragma unroll
            for (int i = 0; i < 8; i++)
                #pragma unroll
                for (int j = 0; j < 8; j++)
                    acc[i][j] += a[i] * b[j];
        }

        if (!last) {
            const int nb = buf ^ 1;
            As[nb][aK + 0][aRow] = aReg.x; As[nb][aK + 1][aRow] = aReg.y;
            As[nb][aK + 2][aRow] = aReg.z; As[nb][aK + 3][aRow] = aReg.w;
            if (TB) {
                Bs[nb][aK + 0][aRow] = bReg.x; Bs[nb][aK + 1][aRow] = bReg.y;
                Bs[nb][aK + 2][aRow] = bReg.z; Bs[nb][aK + 3][aRow] = bReg.w;
            } else {
                *(float4*)&Bs[nb][nK][nC] = bReg;
            }
            __syncthreads();
            buf = nb;
        }
    }

    // epilogue
    #pragma unroll
    for (int i = 0; i < 8; i++) {
        long long r = rowBase + ty + i;
        float* crow = C + r * N + colBase + tx;
        const float* srow = ADDSRC ? (srcp + r * N + colBase + tx) : (const float*)0;
        float4 o0, o1;
        #pragma unroll
        for (int j = 0; j < 8; j++) {
            float vv = alpha * acc[i][j];
            if (bias) vv += bias[colBase + tx + j];
            if (ADDSRC) vv += srow[j];
            if (RELU) vv = fmaxf(vv, 0.0f);
            if (j < 4) ((float*)&o0)[j] = vv; else ((float*)&o1)[j - 4] = vv;
        }
        *(float4*)crow = o0;
        *(float4*)(crow + 4) = o1;
    }
}

// ---------------------------------------------------------------------------
// Output head (ODIM = 1): one warp per row
// ---------------------------------------------------------------------------
__global__ __launch_bounds__(256) void out_kernel(
    const float* __restrict__ x, const float* __restrict__ ow,
    const float* __restrict__ ob, float* __restrict__ out)
{
    int warp = threadIdx.x >> 5, lane = threadIdx.x & 31;
    long long row = (long long)blockIdx.x * 8 + warp;
    const float* xr = x + row * cD;
    float s = 0.0f;
    #pragma unroll
    for (int j = lane; j < cD; j += 32) s += xr[j] * ow[j];
    #pragma unroll
    for (int o = 16; o; o >>= 1) s += __shfl_xor_sync(0xffffffffu, s, o);
    if (lane == 0) out[row] = s + ob[0];
}

// ---------------------------------------------------------------------------
// Launch
// ---------------------------------------------------------------------------
extern "C" void kernel_launch(void* const* d_in, const int* in_sizes, int n_in,
                              void* d_out, int out_size)
{
    (void)in_sizes; (void)n_in; (void)out_size;
    const float* z    = (const float*)d_in[0];
    const float* c    = (const float*)d_in[1];
    const float* encw = (const float*)d_in[2];
    const float* encb = (const float*)d_in[3];
    const float* beta = (const float*)d_in[4];
    const float* wq   = (const float*)d_in[5];
    const float* bq   = (const float*)d_in[6];
    const float* wk   = (const float*)d_in[7];
    const float* bk   = (const float*)d_in[8];
    const float* wv   = (const float*)d_in[9];
    const float* bv   = (const float*)d_in[10];
    const float* ln1w = (const float*)d_in[11];
    const float* ln1b = (const float*)d_in[12];
    const float* ln2w = (const float*)d_in[13];
    const float* ln2b = (const float*)d_in[14];
    const float* f1w  = (const float*)d_in[15];
    const float* f1b  = (const float*)d_in[16];
    const float* f2w  = (const float*)d_in[17];
    const float* f2b  = (const float*)d_in[18];
    const float* ow   = (const float*)d_in[19];
    const float* ob   = (const float*)d_in[20];

    float *x, *xn, *q, *k, *v, *ao, *att, *h, *tab;
    cudaGetSymbolAddress((void**)&x,   g_x);
    cudaGetSymbolAddress((void**)&xn,  g_xn);
    cudaGetSymbolAddress((void**)&q,   g_q);
    cudaGetSymbolAddress((void**)&k,   g_k);
    cudaGetSymbolAddress((void**)&v,   g_v);
    cudaGetSymbolAddress((void**)&ao,  g_ao);
    cudaGetSymbolAddress((void**)&att, g_att);
    cudaGetSymbolAddress((void**)&h,   g_h);
    cudaGetSymbolAddress((void**)&tab, g_tab);

    const long long SD = (long long)cS * cD;
    const long long SSq = (long long)cS * cS;
    const float inv_sqrt_d = 0.044194173824159216f; // 1/sqrt(512)

    enc_kernel<<<(cB * cS * cD + 255) / 256, 256>>>(z, c, encw, encb, x);

    for (int l = 0; l < cL; l++) {
        const float* wql = wq + (long long)l * cD * cD;
        const float* wkl = wk + (long long)l * cD * cD;
        const float* wvl = wv + (long long)l * cD * cD;

        ln_kernel<<<cM, 128>>>(x, (const float*)0, ln1w + l * cD, ln1b + l * cD, xn);

        dim3 gQKV(cD / 128, cM / 128, 1);
        gemm128<true, false, false><<<gQKV, 256>>>(xn, wql, bq + l * cD, (const float*)0, q,
                                                   cM, cD, cD, 0, 0, 0, 1.0f);
        gemm128<true, false, false><<<gQKV, 256>>>(xn, wkl, bk + l * cD, (const float*)0, k,
                                                   cM, cD, cD, 0, 0, 0, 1.0f);
        gemm128<true, false, false><<<gQKV, 256>>>(xn, wvl, bv + l * cD, (const float*)0, v,
                                                   cM, cD, cD, 0, 0, 0, 1.0f);

        btab_kernel<<<cS / 256, 256>>>(beta, l, tab);

        dim3 gS(cS / 128, cS / 128, cB);
        gemm128<true, false, false><<<gS, 256>>>(q, k, (const float*)0, (const float*)0, att,
                                                 cS, cS, cD, SD, SD, SSq, inv_sqrt_d);

        softmax_kernel<<<dim3(cS, cB), 256>>>(att, tab);

        dim3 gV(cD / 128, cS / 128, cB);
        gemm128<false, false, false><<<gV, 256>>>(att, v, (const float*)0, (const float*)0, ao,
                                                  cS, cD, cS, SSq, SD, SD, 1.0f);

        ln_kernel<<<cM, 128>>>(x, ao, ln1w + l * cD, ln1b + l * cD, x);
        ln_kernel<<<cM, 128>>>(x, (const float*)0, ln2w + l * cD, ln2b + l * cD, xn);

        dim3 g1(cF / 128, cM / 128, 1);
        gemm128<true, true, false><<<g1, 256>>>(xn, f1w + (long long)l * cF * cD, f1b + l * cF,
                                                (const float*)0, h, cM, cF, cD, 0, 0, 0, 1.0f);
        dim3 g2(cD / 128, cM / 128, 1);
        gemm128<true, false, true><<<g2, 256>>>(h, f2w + (long long)l * cD * cF, f2b + l * cD,
                                                x, x, cM, cD, cF, 0, 0, 0, 1.0f);
    }

    out_kernel<<<cM / 8, 256>>>(x, ow, ob, (float*)d_out);
}

// round 4
// speedup vs baseline: 1.3524x; 1.0814x over previous
#include <cuda_runtime.h>
#include <math.h>

// Problem constants
static const int cB = 8;
static const int cS = 2048;
static const int cD = 512;
static const int cL = 6;
static const int cF = 2048;   // 4*D
static const int cM = cB * cS; // 16384 rows

// ---------------------------------------------------------------------------
// Scratch (static device allocations; no cudaMalloc allowed)
// ---------------------------------------------------------------------------
__device__ float g_x  [cB * cS * cD];
__device__ float g_xn [cB * cS * cD];
__device__ float g_q  [cB * cS * cD];
__device__ float g_k  [cB * cS * cD];
__device__ float g_v  [cB * cS * cD];
__device__ float g_ao [cB * cS * cD];
__device__ float g_att[(long long)cB * cS * cS];
__device__ float g_h  [(long long)cM * cF];
__device__ float g_tab[cS];

// ---------------------------------------------------------------------------
// Encoder: x = z*enc_w[:,0] + c*enc_w[:,1] + enc_b + posenc
// ---------------------------------------------------------------------------
__global__ void enc_kernel(const float* __restrict__ z, const float* __restrict__ c,
                           const float* __restrict__ ew, const float* __restrict__ eb,
                           float* __restrict__ x)
{
    long long idx = (long long)blockIdx.x * blockDim.x + threadIdx.x;
    if (idx >= (long long)cB * cS * cD) return;
    int d = (int)(idx & (cD - 1));
    long long bs = idx >> 9;
    int s = (int)(bs & (cS - 1));
    const float factor = -1.7988946039015984e-2f;
    float div = expf((float)(2 * (d >> 1)) * factor);
    float ang = (float)s * div;
    float pe = (d & 1) ? cosf(ang) : sinf(ang);
    x[idx] = z[bs] * ew[2 * d] + c[bs] * ew[2 * d + 1] + eb[d] + pe;
}

// ---------------------------------------------------------------------------
// Attention bias table
// ---------------------------------------------------------------------------
__global__ void btab_kernel(const float* __restrict__ beta, int l, float* __restrict__ tab)
{
    int t = blockIdx.x * blockDim.x + threadIdx.x;
    if (t < cS) {
        const float TWO_PI = 6.283185307179586476925f;
        float a0 = TWO_PI * (float)t / 24.0f;
        float a1 = TWO_PI * (float)t / 720.0f;
        tab[t] = beta[2 * l] * cosf(a0) + beta[2 * l + 1] * cosf(a1);
    }
}

// ---------------------------------------------------------------------------
// LayerNorm over D=512
// ---------------------------------------------------------------------------
__global__ __launch_bounds__(128) void ln_kernel(
    const float* __restrict__ x, const float* __restrict__ res,
    const float* __restrict__ w, const float* __restrict__ b,
    float* __restrict__ out)
{
    long long off = (long long)blockIdx.x * cD + threadIdx.x * 4;
    float4 v = *(const float4*)(x + off);
    if (res) {
        float4 r = *(const float4*)(res + off);
        v.x += r.x; v.y += r.y; v.z += r.z; v.w += r.w;
    }
    int lane = threadIdx.x & 31, warp = threadIdx.x >> 5;
    __shared__ float red1[4];
    __shared__ float red2[4];

    float s = v.x + v.y + v.z + v.w;
    #pragma unroll
    for (int o = 16; o; o >>= 1) s += __shfl_xor_sync(0xffffffffu, s, o);
    if (lane == 0) red1[warp] = s;
    __syncthreads();
    float mean = (red1[0] + red1[1] + red1[2] + red1[3]) * (1.0f / 512.0f);

    float d0 = v.x - mean, d1 = v.y - mean, d2 = v.z - mean, d3 = v.w - mean;
    float q = d0 * d0 + d1 * d1 + d2 * d2 + d3 * d3;
    #pragma unroll
    for (int o = 16; o; o >>= 1) q += __shfl_xor_sync(0xffffffffu, q, o);
    if (lane == 0) red2[warp] = q;
    __syncthreads();
    float var = (red2[0] + red2[1] + red2[2] + red2[3]) * (1.0f / 512.0f);
    float rs = rsqrtf(var + 1e-5f);

    float4 wv = *(const float4*)(w + threadIdx.x * 4);
    float4 bv = *(const float4*)(b + threadIdx.x * 4);
    float4 o4;
    o4.x = d0 * rs * wv.x + bv.x;
    o4.y = d1 * rs * wv.y + bv.y;
    o4.z = d2 * rs * wv.z + bv.z;
    o4.w = d3 * rs * wv.w + bv.w;
    *(float4*)(out + off) = o4;
}

// ---------------------------------------------------------------------------
// Softmax with distance bias
// ---------------------------------------------------------------------------
__global__ __launch_bounds__(256) void softmax_kernel(float* __restrict__ att,
                                                      const float* __restrict__ tab)
{
    __shared__ float buf[cS];
    __shared__ float red[8];
    int i = blockIdx.x, b = blockIdx.y;
    float* row = att + ((long long)b * cS + i) * cS;
    int tid = threadIdx.x;

    float mx = -3.4e38f;
    for (int j = tid; j < cS; j += 256) {
        int d = i - j; if (d < 0) d = -d;
        float vv = row[j] + tab[d];
        buf[j] = vv;
        mx = fmaxf(mx, vv);
    }
    #pragma unroll
    for (int o = 16; o; o >>= 1) mx = fmaxf(mx, __shfl_xor_sync(0xffffffffu, mx, o));
    if ((tid & 31) == 0) red[tid >> 5] = mx;
    __syncthreads();
    float m = red[0];
    #pragma unroll
    for (int w2 = 1; w2 < 8; w2++) m = fmaxf(m, red[w2]);
    __syncthreads();

    float sum = 0.0f;
    for (int j = tid; j < cS; j += 256) {
        float e = expf(buf[j] - m);
        buf[j] = e;
        sum += e;
    }
    #pragma unroll
    for (int o = 16; o; o >>= 1) sum += __shfl_xor_sync(0xffffffffu, sum, o);
    if ((tid & 31) == 0) red[tid >> 5] = sum;
    __syncthreads();
    float tot = 0.0f;
    #pragma unroll
    for (int w2 = 0; w2 < 8; w2++) tot += red[w2];
    float inv = 1.0f / tot;
    for (int j = tid; j < cS; j += 256) row[j] = buf[j] * inv;
}

// ---------------------------------------------------------------------------
// Batched GEMM: C = alpha * A @ op(B) (+bias) (+src) (relu)
//   A: [M,K] row-major, op(B)=B^T if TB (B is [N,K]) else B ([K,N])
//   128x128x8 tiles, 256 threads, 8x8 per thread (split 4+4 at stride 64
//   for conflict-free LDS.128 fragment loads), double-buffered smem.
// ---------------------------------------------------------------------------
template<bool TB, bool RELU, bool ADDSRC>
__global__ __launch_bounds__(256) void gemm128(
    const float* __restrict__ A, const float* __restrict__ B,
    const float* __restrict__ bias, const float* __restrict__ src,
    float* __restrict__ C, int M, int N, int K,
    long long bsA, long long bsB, long long bsC, float alpha)
{
    A += (long long)blockIdx.z * bsA;
    B += (long long)blockIdx.z * bsB;
    C += (long long)blockIdx.z * bsC;
    const float* srcp = ADDSRC ? (src + (long long)blockIdx.z * bsC) : (const float*)0;

    __shared__ float As[2][8][128];
    __shared__ float Bs[2][8][128];

    const int tid = threadIdx.x;
    const int rowBase = blockIdx.y * 128, colBase = blockIdx.x * 128;

    // loaders
    const int aRow = tid >> 1;           // 0..127
    const int aK   = (tid & 1) << 2;     // 0 or 4
    const int nK   = tid >> 5;           // 0..7   (NN path)
    const int nC   = (tid & 31) << 2;    // 0..124 (NN path)

    const float* Aptr  = A + (long long)(rowBase + aRow) * K + aK;
    const float* BptrT = B + (long long)(colBase + aRow) * K + aK;
    const float* BptrN = B + (long long)nK * N + colBase + nC;

    // initial tile -> buffer 0
    {
        float4 av = *(const float4*)Aptr;
        As[0][aK + 0][aRow] = av.x; As[0][aK + 1][aRow] = av.y;
        As[0][aK + 2][aRow] = av.z; As[0][aK + 3][aRow] = av.w;
        if (TB) {
            float4 bv = *(const float4*)BptrT;
            Bs[0][aK + 0][aRow] = bv.x; Bs[0][aK + 1][aRow] = bv.y;
            Bs[0][aK + 2][aRow] = bv.z; Bs[0][aK + 3][aRow] = bv.w;
        } else {
            float4 bv = *(const float4*)BptrN;
            *(float4*)&Bs[0][nK][nC] = bv;
        }
    }
    __syncthreads();

    // microtile: rows {ty4..ty4+3, ty4+64..ty4+67}, cols {tx4..tx4+3, tx4+64..tx4+67}
    const int ty4 = (tid >> 4) << 2;   // 0..60 step 4
    const int tx4 = (tid & 15) << 2;   // 0..60 step 4

    float acc[8][8] = {};
    int buf = 0;

    for (int k0 = 0; k0 < K; k0 += 8) {
        const bool last = (k0 + 8 >= K);
        float4 aReg, bReg;
        if (!last) {
            aReg = *(const float4*)(Aptr + k0 + 8);
            bReg = TB ? *(const float4*)(BptrT + k0 + 8)
                      : *(const float4*)(BptrN + (long long)(k0 + 8) * N);
        }

        #pragma unroll
        for (int kk = 0; kk < 8; kk++) {
            float4 a0 = *(const float4*)&As[buf][kk][ty4];
            float4 a1 = *(const float4*)&As[buf][kk][ty4 + 64];
            float4 b0 = *(const float4*)&Bs[buf][kk][tx4];
            float4 b1 = *(const float4*)&Bs[buf][kk][tx4 + 64];
            float a[8] = {a0.x, a0.y, a0.z, a0.w, a1.x, a1.y, a1.z, a1.w};
            float b[8] = {b0.x, b0.y, b0.z, b0.w, b1.x, b1.y, b1.z, b1.w};
            #pragma unroll
            for (int i = 0; i < 8; i++)
                #pragma unroll
                for (int j = 0; j < 8; j++)
                    acc[i][j] += a[i] * b[j];
        }

        if (!last) {
            const int nb = buf ^ 1;
            As[nb][aK + 0][aRow] = aReg.x; As[nb][aK + 1][aRow] = aReg.y;
            As[nb][aK + 2][aRow] = aReg.z; As[nb][aK + 3][aRow] = aReg.w;
            if (TB) {
                Bs[nb][aK + 0][aRow] = bReg.x; Bs[nb][aK + 1][aRow] = bReg.y;
                Bs[nb][aK + 2][aRow] = bReg.z; Bs[nb][aK + 3][aRow] = bReg.w;
            } else {
                *(float4*)&Bs[nb][nK][nC] = bReg;
            }
            __syncthreads();
            buf = nb;
        }
    }

    // epilogue: acc[ih*4+i][jh*4+j] -> (rowBase+ty4+ih*64+i, colBase+tx4+jh*64+j)
    #pragma unroll
    for (int ih = 0; ih < 2; ih++) {
        #pragma unroll
        for (int i = 0; i < 4; i++) {
            long long r = rowBase + ty4 + ih * 64 + i;
            float* crow = C + r * N + colBase;
            const float* srow = ADDSRC ? (srcp + r * N + colBase) : (const float*)0;
            #pragma unroll
            for (int jh = 0; jh < 2; jh++) {
                float4 o;
                #pragma unroll
                for (int j = 0; j < 4; j++) {
                    int col = tx4 + jh * 64 + j;
                    float vv = alpha * acc[ih * 4 + i][jh * 4 + j];
                    if (bias) vv += bias[colBase + col];
                    if (ADDSRC) vv += srow[col];
                    if (RELU) vv = fmaxf(vv, 0.0f);
                    ((float*)&o)[j] = vv;
                }
                *(float4*)(crow + tx4 + jh * 64) = o;
            }
        }
    }
}

// ---------------------------------------------------------------------------
// Output head (ODIM = 1): one warp per row
// ---------------------------------------------------------------------------
__global__ __launch_bounds__(256) void out_kernel(
    const float* __restrict__ x, const float* __restrict__ ow,
    const float* __restrict__ ob, float* __restrict__ out)
{
    int warp = threadIdx.x >> 5, lane = threadIdx.x & 31;
    long long row = (long long)blockIdx.x * 8 + warp;
    const float* xr = x + row * cD;
    float s = 0.0f;
    #pragma unroll
    for (int j = lane; j < cD; j += 32) s += xr[j] * ow[j];
    #pragma unroll
    for (int o = 16; o; o >>= 1) s += __shfl_xor_sync(0xffffffffu, s, o);
    if (lane == 0) out[row] = s + ob[0];
}

// ---------------------------------------------------------------------------
// Launch
// ---------------------------------------------------------------------------
extern "C" void kernel_launch(void* const* d_in, const int* in_sizes, int n_in,
                              void* d_out, int out_size)
{
    (void)in_sizes; (void)n_in; (void)out_size;
    const float* z    = (const float*)d_in[0];
    const float* c    = (const float*)d_in[1];
    const float* encw = (const float*)d_in[2];
    const float* encb = (const float*)d_in[3];
    const float* beta = (const float*)d_in[4];
    const float* wq   = (const float*)d_in[5];
    const float* bq   = (const float*)d_in[6];
    const float* wk   = (const float*)d_in[7];
    const float* bk   = (const float*)d_in[8];
    const float* wv   = (const float*)d_in[9];
    const float* bv   = (const float*)d_in[10];
    const float* ln1w = (const float*)d_in[11];
    const float* ln1b = (const float*)d_in[12];
    const float* ln2w = (const float*)d_in[13];
    const float* ln2b = (const float*)d_in[14];
    const float* f1w  = (const float*)d_in[15];
    const float* f1b  = (const float*)d_in[16];
    const float* f2w  = (const float*)d_in[17];
    const float* f2b  = (const float*)d_in[18];
    const float* ow   = (const float*)d_in[19];
    const float* ob   = (const float*)d_in[20];

    float *x, *xn, *q, *k, *v, *ao, *att, *h, *tab;
    cudaGetSymbolAddress((void**)&x,   g_x);
    cudaGetSymbolAddress((void**)&xn,  g_xn);
    cudaGetSymbolAddress((void**)&q,   g_q);
    cudaGetSymbolAddress((void**)&k,   g_k);
    cudaGetSymbolAddress((void**)&v,   g_v);
    cudaGetSymbolAddress((void**)&ao,  g_ao);
    cudaGetSymbolAddress((void**)&att, g_att);
    cudaGetSymbolAddress((void**)&h,   g_h);
    cudaGetSymbolAddress((void**)&tab, g_tab);

    const long long SD = (long long)cS * cD;
    const long long SSq = (long long)cS * cS;
    const float inv_sqrt_d = 0.044194173824159216f; // 1/sqrt(512)

    enc_kernel<<<(cB * cS * cD + 255) / 256, 256>>>(z, c, encw, encb, x);

    for (int l = 0; l < cL; l++) {
        const float* wql = wq + (long long)l * cD * cD;
        const float* wkl = wk + (long long)l * cD * cD;
        const float* wvl = wv + (long long)l * cD * cD;

        ln_kernel<<<cM, 128>>>(x, (const float*)0, ln1w + l * cD, ln1b + l * cD, xn);

        dim3 gQKV(cD / 128, cM / 128, 1);
        gemm128<true, false, false><<<gQKV, 256>>>(xn, wql, bq + l * cD, (const float*)0, q,
                                                   cM, cD, cD, 0, 0, 0, 1.0f);
        gemm128<true, false, false><<<gQKV, 256>>>(xn, wkl, bk + l * cD, (const float*)0, k,
                                                   cM, cD, cD, 0, 0, 0, 1.0f);
        gemm128<true, false, false><<<gQKV, 256>>>(xn, wvl, bv + l * cD, (const float*)0, v,
                                                   cM, cD, cD, 0, 0, 0, 1.0f);

        btab_kernel<<<cS / 256, 256>>>(beta, l, tab);

        dim3 gS(cS / 128, cS / 128, cB);
        gemm128<true, false, false><<<gS, 256>>>(q, k, (const float*)0, (const float*)0, att,
                                                 cS, cS, cD, SD, SD, SSq, inv_sqrt_d);

        softmax_kernel<<<dim3(cS, cB), 256>>>(att, tab);

        dim3 gV(cD / 128, cS / 128, cB);
        gemm128<false, false, false><<<gV, 256>>>(att, v, (const float*)0, (const float*)0, ao,
                                                  cS, cD, cS, SSq, SD, SD, 1.0f);

        ln_kernel<<<cM, 128>>>(x, ao, ln1w + l * cD, ln1b + l * cD, x);
        ln_kernel<<<cM, 128>>>(x, (const float*)0, ln2w + l * cD, ln2b + l * cD, xn);

        dim3 g1(cF / 128, cM / 128, 1);
        gemm128<true, true, false><<<g1, 256>>>(xn, f1w + (long long)l * cF * cD, f1b + l * cF,
                                                (const float*)0, h, cM, cF, cD, 0, 0, 0, 1.0f);
        dim3 g2(cD / 128, cM / 128, 1);
        gemm128<true, false, true><<<g2, 256>>>(h, f2w + (long long)l * cD * cF, f2b + l * cD,
                                                x, x, cM, cD, cF, 0, 0, 0, 1.0f);
    }

    out_kernel<<<cM / 8, 256>>>(x, ow, ob, (float*)d_out);
}

// round 7
// speedup vs baseline: 2.4729x; 1.8285x over previous
#include <cuda_runtime.h>
#include <cuda_bf16.h>
#include <stdint.h>
#include <math.h>

// Problem constants
static const int cB = 8;
static const int cS = 2048;
static const int cD = 512;
static const int cL = 6;
static const int cF = 2048;   // 4*D
static const int cM = cB * cS; // 16384 rows

// ---------------------------------------------------------------------------
// Scratch (static device allocations; no cudaMalloc allowed)
// ---------------------------------------------------------------------------
__device__ float g_x  [cM * cD];
__device__ float g_ao [cM * cD];
__device__ float g_att[(long long)cB * cS * cS];
__device__ float g_tab[cS];

__device__ __nv_bfloat16 g_xnh[cM * cD], g_xnl[cM * cD];
__device__ __nv_bfloat16 g_qh [cM * cD], g_ql [cM * cD];
__device__ __nv_bfloat16 g_kh [cM * cD], g_kl [cM * cD];
__device__ __nv_bfloat16 g_vh [cM * cD], g_vl [cM * cD];
__device__ __nv_bfloat16 g_vth[cM * cD], g_vtl[cM * cD];
__device__ __nv_bfloat16 g_ph [(long long)cB * cS * cS], g_pl[(long long)cB * cS * cS];
__device__ __nv_bfloat16 g_hh [(long long)cM * cF],      g_hl[(long long)cM * cF];
__device__ __nv_bfloat16 g_wqh[cD * cD], g_wql[cD * cD];
__device__ __nv_bfloat16 g_wkh[cD * cD], g_wkl[cD * cD];
__device__ __nv_bfloat16 g_wvh[cD * cD], g_wvl[cD * cD];
__device__ __nv_bfloat16 g_f1h[cF * cD], g_f1l[cF * cD];
__device__ __nv_bfloat16 g_f2h[cD * cF], g_f2l[cD * cF];

// ---------------------------------------------------------------------------
// Portable PTX helpers (sm_80-level: mma.sync / ldmatrix / cp.async)
// ---------------------------------------------------------------------------
__device__ __forceinline__ uint32_t smem_to_u32(const void* p) {
    uint32_t a;
    asm("{ .reg .u64 t; cvta.to.shared.u64 t, %1; cvt.u32.u64 %0, t; }" : "=r"(a) : "l"(p));
    return a;
}
__device__ __forceinline__ void cp_async16(uint32_t saddr, const void* gaddr) {
    asm volatile("cp.async.cg.shared.global [%0], [%1], 16;" :: "r"(saddr), "l"(gaddr));
}
__device__ __forceinline__ void cp_commit() {
    asm volatile("cp.async.commit_group;");
}
template<int N>
__device__ __forceinline__ void cp_wait() {
    asm volatile("cp.async.wait_group %0;" :: "n"(N));
}
__device__ __forceinline__ void ldsm4(uint32_t* r, uint32_t addr) {
    asm volatile("ldmatrix.sync.aligned.m8n8.x4.shared.b16 {%0,%1,%2,%3}, [%4];"
        : "=r"(r[0]), "=r"(r[1]), "=r"(r[2]), "=r"(r[3]) : "r"(addr));
}
__device__ __forceinline__ void mma16816(float* c, const uint32_t* a, uint32_t b0, uint32_t b1) {
    asm volatile(
        "mma.sync.aligned.m16n8k16.row.col.f32.bf16.bf16.f32 "
        "{%0,%1,%2,%3}, {%4,%5,%6,%7}, {%8,%9}, {%0,%1,%2,%3};"
        : "+f"(c[0]), "+f"(c[1]), "+f"(c[2]), "+f"(c[3])
        : "r"(a[0]), "r"(a[1]), "r"(a[2]), "r"(a[3]), "r"(b0), "r"(b1));
}

// ---------------------------------------------------------------------------
// Encoder
// ---------------------------------------------------------------------------
__global__ void enc_kernel(const float* __restrict__ z, const float* __restrict__ c,
                           const float* __restrict__ ew, const float* __restrict__ eb,
                           float* __restrict__ x)
{
    long long idx = (long long)blockIdx.x * blockDim.x + threadIdx.x;
    if (idx >= (long long)cM * cD) return;
    int d = (int)(idx & (cD - 1));
    long long bs = idx >> 9;
    int s = (int)(bs & (cS - 1));
    const float factor = -1.7988946039015984e-2f;
    float div = expf((float)(2 * (d >> 1)) * factor);
    float ang = (float)s * div;
    float pe = (d & 1) ? cosf(ang) : sinf(ang);
    x[idx] = z[bs] * ew[2 * d] + c[bs] * ew[2 * d + 1] + eb[d] + pe;
}

// ---------------------------------------------------------------------------
// Attention bias table
// ---------------------------------------------------------------------------
__global__ void btab_kernel(const float* __restrict__ beta, int l, float* __restrict__ tab)
{
    int t = blockIdx.x * blockDim.x + threadIdx.x;
    if (t < cS) {
        const float TWO_PI = 6.283185307179586476925f;
        tab[t] = beta[2 * l] * cosf(TWO_PI * (float)t / 24.0f)
               + beta[2 * l + 1] * cosf(TWO_PI * (float)t / 720.0f);
    }
}

// ---------------------------------------------------------------------------
// fp32 -> (hi, lo) bf16 split
// ---------------------------------------------------------------------------
__global__ void cvt_kernel(const float* __restrict__ x,
                           __nv_bfloat16* __restrict__ h, __nv_bfloat16* __restrict__ l, int n)
{
    int i = blockIdx.x * blockDim.x + threadIdx.x;
    if (i < n) {
        float v = x[i];
        __nv_bfloat16 hi = __float2bfloat16(v);
        h[i] = hi;
        l[i] = __float2bfloat16(v - __bfloat162float(hi));
    }
}

// ---------------------------------------------------------------------------
// LayerNorm over D=512, optional fp32 out and/or hi/lo bf16 out
// ---------------------------------------------------------------------------
__global__ __launch_bounds__(128) void ln_kernel(
    const float* __restrict__ x, const float* __restrict__ res,
    const float* __restrict__ w, const float* __restrict__ b,
    float* __restrict__ out, __nv_bfloat16* __restrict__ oh, __nv_bfloat16* __restrict__ ol)
{
    long long off = (long long)blockIdx.x * cD + threadIdx.x * 4;
    float4 v = *(const float4*)(x + off);
    if (res) {
        float4 r = *(const float4*)(res + off);
        v.x += r.x; v.y += r.y; v.z += r.z; v.w += r.w;
    }
    int lane = threadIdx.x & 31, warp = threadIdx.x >> 5;
    __shared__ float red1[4];
    __shared__ float red2[4];

    float s = v.x + v.y + v.z + v.w;
    #pragma unroll
    for (int o = 16; o; o >>= 1) s += __shfl_xor_sync(0xffffffffu, s, o);
    if (lane == 0) red1[warp] = s;
    __syncthreads();
    float mean = (red1[0] + red1[1] + red1[2] + red1[3]) * (1.0f / 512.0f);

    float d0 = v.x - mean, d1 = v.y - mean, d2 = v.z - mean, d3 = v.w - mean;
    float q = d0 * d0 + d1 * d1 + d2 * d2 + d3 * d3;
    #pragma unroll
    for (int o = 16; o; o >>= 1) q += __shfl_xor_sync(0xffffffffu, q, o);
    if (lane == 0) red2[warp] = q;
    __syncthreads();
    float var = (red2[0] + red2[1] + red2[2] + red2[3]) * (1.0f / 512.0f);
    float rs = rsqrtf(var + 1e-5f);

    float4 wv = *(const float4*)(w + threadIdx.x * 4);
    float4 bv = *(const float4*)(b + threadIdx.x * 4);
    float o4[4];
    o4[0] = d0 * rs * wv.x + bv.x;
    o4[1] = d1 * rs * wv.y + bv.y;
    o4[2] = d2 * rs * wv.z + bv.z;
    o4[3] = d3 * rs * wv.w + bv.w;
    if (out) *(float4*)(out + off) = *(float4*)o4;
    if (oh) {
        __nv_bfloat16 hv[4], lv[4];
        #pragma unroll
        for (int i = 0; i < 4; i++) {
            hv[i] = __float2bfloat16(o4[i]);
            lv[i] = __float2bfloat16(o4[i] - __bfloat162float(hv[i]));
        }
        *(uint2*)(oh + off) = *(uint2*)hv;
        *(uint2*)(ol + off) = *(uint2*)lv;
    }
}

// ---------------------------------------------------------------------------
// Softmax with distance bias: fp32 logits in, hi/lo bf16 probs out
// ---------------------------------------------------------------------------
__global__ __launch_bounds__(256) void softmax_kernel(
    const float* __restrict__ att, const float* __restrict__ tab,
    __nv_bfloat16* __restrict__ ph, __nv_bfloat16* __restrict__ pl)
{
    __shared__ float buf[cS];
    __shared__ float red[8];
    int i = blockIdx.x, b = blockIdx.y;
    long long roff = ((long long)b * cS + i) * cS;
    const float* row = att + roff;
    int tid = threadIdx.x;

    float mx = -3.4e38f;
    for (int j = tid; j < cS; j += 256) {
        int d = i - j; if (d < 0) d = -d;
        float vv = row[j] + tab[d];
        buf[j] = vv;
        mx = fmaxf(mx, vv);
    }
    #pragma unroll
    for (int o = 16; o; o >>= 1) mx = fmaxf(mx, __shfl_xor_sync(0xffffffffu, mx, o));
    if ((tid & 31) == 0) red[tid >> 5] = mx;
    __syncthreads();
    float m = red[0];
    #pragma unroll
    for (int w2 = 1; w2 < 8; w2++) m = fmaxf(m, red[w2]);
    __syncthreads();

    float sum = 0.0f;
    for (int j = tid; j < cS; j += 256) {
        float e = expf(buf[j] - m);
        buf[j] = e;
        sum += e;
    }
    #pragma unroll
    for (int o = 16; o; o >>= 1) sum += __shfl_xor_sync(0xffffffffu, sum, o);
    if ((tid & 31) == 0) red[tid >> 5] = sum;
    __syncthreads();
    float tot = 0.0f;
    #pragma unroll
    for (int w2 = 0; w2 < 8; w2++) tot += red[w2];
    float inv = 1.0f / tot;
    for (int j = tid; j < cS; j += 256) {
        float p = buf[j] * inv;
        __nv_bfloat16 hv = __float2bfloat16(p);
        ph[roff + j] = hv;
        pl[roff + j] = __float2bfloat16(p - __bfloat162float(hv));
    }
}

// ---------------------------------------------------------------------------
// Transpose V (hi/lo): [b, s, d] -> [b, d, s]
// ---------------------------------------------------------------------------
__global__ __launch_bounds__(256) void tr_kernel(
    const __nv_bfloat16* __restrict__ sh, const __nv_bfloat16* __restrict__ sl,
    __nv_bfloat16* __restrict__ dh, __nv_bfloat16* __restrict__ dl)
{
    __shared__ __nv_bfloat16 th[32][33], tl[32][33];
    int b = blockIdx.z;
    int d0 = blockIdx.x * 32, s0 = blockIdx.y * 32;
    int tx = threadIdx.x & 31, ty = threadIdx.x >> 5;
    #pragma unroll
    for (int yy = 0; yy < 4; yy++) {
        int s = s0 + ty + yy * 8;
        long long g = ((long long)b * cS + s) * cD + d0 + tx;
        th[ty + yy * 8][tx] = sh[g];
        tl[ty + yy * 8][tx] = sl[g];
    }
    __syncthreads();
    #pragma unroll
    for (int yy = 0; yy < 4; yy++) {
        int d = d0 + ty + yy * 8;
        long long g = ((long long)b * cD + d) * cS + s0 + tx;
        dh[g] = th[tx][ty + yy * 8];
        dl[g] = tl[tx][ty + yy * 8];
    }
}

// ---------------------------------------------------------------------------
// Tensor-core GEMM via mma.sync (bf16, 3-term hi/lo, fp32 accum):
//   C = alpha * (A @ B^T) (+bias) (+src) (relu)
//   A: [M,K] bf16 hi/lo (K-major), B: [N,K] bf16 hi/lo (K-major)
//   CTA tile 128x128x32, 8 warps (4m x 2n), warp tile 32x64.
//   Smem: padded rows of 40 bf16 (80B stride -> conflict-free ldmatrix).
//   cp.async double-buffered.
// ---------------------------------------------------------------------------
static const int TPAD = 40;                       // padded k-stride (elems)
static const int TILE_BYTES = 128 * TPAD * 2;     // 10240 per tile buffer
static const int O_AH = 0;
static const int O_AL = O_AH + 2 * TILE_BYTES;
static const int O_BH = O_AL + 2 * TILE_BYTES;
static const int O_BL = O_BH + 2 * TILE_BYTES;
static const int T_SMEM = O_BL + 2 * TILE_BYTES;  // 81920 bytes

template<bool OUTF32, bool OUTHL, bool RELU, bool ADDSRC>
__global__ __launch_bounds__(256, 2) void tgemm(
    const __nv_bfloat16* __restrict__ Ah, const __nv_bfloat16* __restrict__ Al,
    const __nv_bfloat16* __restrict__ Bh, const __nv_bfloat16* __restrict__ Bl,
    const float* __restrict__ bias, const float* __restrict__ src,
    float* __restrict__ C, __nv_bfloat16* __restrict__ Ch, __nv_bfloat16* __restrict__ Cl,
    int N, int K, long long bsA, long long bsB, long long bsC, float alpha)
{
    extern __shared__ __align__(16) char smem[];
    const uint32_t sb = smem_to_u32(smem);
    const int tid = threadIdx.x;
    const int wid = tid >> 5, lane = tid & 31;

    Ah += (long long)blockIdx.z * bsA;  Al += (long long)blockIdx.z * bsA;
    Bh += (long long)blockIdx.z * bsB;  Bl += (long long)blockIdx.z * bsB;
    const long long zC = (long long)blockIdx.z * bsC;

    const int rowBase = blockIdx.y * 128;
    const int colBase = blockIdx.x * 128;

    // loader mapping: row = tid>>1 (0..127), off = (tid&1)*16 elems
    const int ldRow = tid >> 1;
    const int ldOff = (tid & 1) << 4;
    const long long gA = (long long)(rowBase + ldRow) * K + ldOff;
    const long long gB = (long long)(colBase + ldRow) * K + ldOff;
    const uint32_t sOff = (uint32_t)(ldRow * TPAD + ldOff) * 2;

    const int nkt = K >> 5;

    // prologue: k-tile 0 -> buffer 0
    {
        const long long a0 = gA, b0 = gB;
        cp_async16(sb + O_AH + sOff,      Ah + a0);
        cp_async16(sb + O_AH + sOff + 16, Ah + a0 + 8);
        cp_async16(sb + O_AL + sOff,      Al + a0);
        cp_async16(sb + O_AL + sOff + 16, Al + a0 + 8);
        cp_async16(sb + O_BH + sOff,      Bh + b0);
        cp_async16(sb + O_BH + sOff + 16, Bh + b0 + 8);
        cp_async16(sb + O_BL + sOff,      Bl + b0);
        cp_async16(sb + O_BL + sOff + 16, Bl + b0 + 8);
        cp_commit();
    }

    // warp / lane geometry
    const int wm = wid >> 1;        // 0..3
    const int wn = wid & 1;         // 0..1
    const int lq = lane >> 3, lr = lane & 7;
    const int lrow = lr + (lq & 1) * 8;
    const int lcol = (lq >> 1) * 8;
    // ldmatrix region offsets (bytes): A region (mi, ks), B region (np, ks)
    const uint32_t aBase = (uint32_t)((wm * 32 + lrow) * TPAD + lcol) * 2;
    const uint32_t bBase = (uint32_t)((wn * 64 + lrow) * TPAD + lcol) * 2;

    float acc[16][4];
    #pragma unroll
    for (int i = 0; i < 16; i++)
        #pragma unroll
        for (int j = 0; j < 4; j++) acc[i][j] = 0.0f;

    for (int kt = 0; kt < nkt; kt++) {
        const int buf = kt & 1;
        if (kt + 1 < nkt) {
            const int nb = (kt + 1) & 1;
            const long long a0 = gA + (long long)(kt + 1) * 32;
            const long long b0 = gB + (long long)(kt + 1) * 32;
            const uint32_t bo = (uint32_t)nb * TILE_BYTES + sOff;
            cp_async16(sb + O_AH + bo,      Ah + a0);
            cp_async16(sb + O_AH + bo + 16, Ah + a0 + 8);
            cp_async16(sb + O_AL + bo,      Al + a0);
            cp_async16(sb + O_AL + bo + 16, Al + a0 + 8);
            cp_async16(sb + O_BH + bo,      Bh + b0);
            cp_async16(sb + O_BH + bo + 16, Bh + b0 + 8);
            cp_async16(sb + O_BL + bo,      Bl + b0);
            cp_async16(sb + O_BL + bo + 16, Bl + b0 + 8);
            cp_commit();
            cp_wait<1>();
        } else {
            cp_wait<0>();
        }
        __syncthreads();

        const uint32_t ah0 = sb + O_AH + (uint32_t)buf * TILE_BYTES + aBase;
        const uint32_t al0 = sb + O_AL + (uint32_t)buf * TILE_BYTES + aBase;
        const uint32_t bh0 = sb + O_BH + (uint32_t)buf * TILE_BYTES + bBase;
        const uint32_t bl0 = sb + O_BL + (uint32_t)buf * TILE_BYTES + bBase;

        #pragma unroll
        for (int ks = 0; ks < 2; ks++) {
            uint32_t ah[2][4], al[2][4];
            ldsm4(ah[0], ah0 + ks * 32);
            ldsm4(ah[1], ah0 + 16 * TPAD * 2 + ks * 32);
            ldsm4(al[0], al0 + ks * 32);
            ldsm4(al[1], al0 + 16 * TPAD * 2 + ks * 32);
            #pragma unroll
            for (int np = 0; np < 4; np++) {
                uint32_t bh[4], bl[4];
                ldsm4(bh, bh0 + np * 16 * TPAD * 2 + ks * 32);
                ldsm4(bl, bl0 + np * 16 * TPAD * 2 + ks * 32);
                #pragma unroll
                for (int mi = 0; mi < 2; mi++) {
                    #pragma unroll
                    for (int nt = 0; nt < 2; nt++) {
                        float* cf = acc[mi * 8 + np * 2 + nt];
                        mma16816(cf, ah[mi], bh[nt], bh[nt + 2]);
                        mma16816(cf, ah[mi], bl[nt], bl[nt + 2]);
                        mma16816(cf, al[mi], bh[nt], bh[nt + 2]);
                    }
                }
            }
        }
        __syncthreads();
    }

    // Epilogue
    const int eg = lane >> 2, et = (lane & 3) * 2;
    #pragma unroll
    for (int mi = 0; mi < 2; mi++) {
        #pragma unroll
        for (int np = 0; np < 4; np++) {
            #pragma unroll
            for (int nt = 0; nt < 2; nt++) {
                const float* cf = acc[mi * 8 + np * 2 + nt];
                const int col = colBase + wn * 64 + np * 16 + nt * 8 + et;
                #pragma unroll
                for (int hf = 0; hf < 2; hf++) {
                    const long long r = rowBase + wm * 32 + mi * 16 + eg + hf * 8;
                    float v0 = cf[hf * 2 + 0] * alpha;
                    float v1 = cf[hf * 2 + 1] * alpha;
                    if (bias) { v0 += bias[col]; v1 += bias[col + 1]; }
                    if (ADDSRC) {
                        float2 sv = *(const float2*)(src + zC + r * (long long)N + col);
                        v0 += sv.x; v1 += sv.y;
                    }
                    if (RELU) { v0 = fmaxf(v0, 0.0f); v1 = fmaxf(v1, 0.0f); }
                    if (OUTF32) {
                        float2 o; o.x = v0; o.y = v1;
                        *(float2*)(C + zC + r * (long long)N + col) = o;
                    }
                    if (OUTHL) {
                        __nv_bfloat16 h0 = __float2bfloat16(v0);
                        __nv_bfloat16 h1 = __float2bfloat16(v1);
                        __nv_bfloat16 l0 = __float2bfloat16(v0 - __bfloat162float(h0));
                        __nv_bfloat16 l1 = __float2bfloat16(v1 - __bfloat162float(h1));
                        __nv_bfloat16 hp[2] = {h0, h1};
                        __nv_bfloat16 lp[2] = {l0, l1};
                        *(uint32_t*)(Ch + zC + r * (long long)N + col) = *(uint32_t*)hp;
                        *(uint32_t*)(Cl + zC + r * (long long)N + col) = *(uint32_t*)lp;
                    }
                }
            }
        }
    }
}

// ---------------------------------------------------------------------------
// Output head (ODIM = 1)
// ---------------------------------------------------------------------------
__global__ __launch_bounds__(256) void out_kernel(
    const float* __restrict__ x, const float* __restrict__ ow,
    const float* __restrict__ ob, float* __restrict__ out)
{
    int warp = threadIdx.x >> 5, lane = threadIdx.x & 31;
    long long row = (long long)blockIdx.x * 8 + warp;
    const float* xr = x + row * cD;
    float s = 0.0f;
    #pragma unroll
    for (int j = lane; j < cD; j += 32) s += xr[j] * ow[j];
    #pragma unroll
    for (int o = 16; o; o >>= 1) s += __shfl_xor_sync(0xffffffffu, s, o);
    if (lane == 0) out[row] = s + ob[0];
}

// ---------------------------------------------------------------------------
// Launch
// ---------------------------------------------------------------------------
extern "C" void kernel_launch(void* const* d_in, const int* in_sizes, int n_in,
                              void* d_out, int out_size)
{
    (void)in_sizes; (void)n_in; (void)out_size;
    const float* z    = (const float*)d_in[0];
    const float* c    = (const float*)d_in[1];
    const float* encw = (const float*)d_in[2];
    const float* encb = (const float*)d_in[3];
    const float* beta = (const float*)d_in[4];
    const float* wq   = (const float*)d_in[5];
    const float* bq   = (const float*)d_in[6];
    const float* wk   = (const float*)d_in[7];
    const float* bk   = (const float*)d_in[8];
    const float* wv   = (const float*)d_in[9];
    const float* bv   = (const float*)d_in[10];
    const float* ln1w = (const float*)d_in[11];
    const float* ln1b = (const float*)d_in[12];
    const float* ln2w = (const float*)d_in[13];
    const float* ln2b = (const float*)d_in[14];
    const float* f1w  = (const float*)d_in[15];
    const float* f1b  = (const float*)d_in[16];
    const float* f2w  = (const float*)d_in[17];
    const float* f2b  = (const float*)d_in[18];
    const float* ow   = (const float*)d_in[19];
    const float* ob   = (const float*)d_in[20];

    float *x, *ao, *att, *tab;
    cudaGetSymbolAddress((void**)&x,   g_x);
    cudaGetSymbolAddress((void**)&ao,  g_ao);
    cudaGetSymbolAddress((void**)&att, g_att);
    cudaGetSymbolAddress((void**)&tab, g_tab);
    __nv_bfloat16 *xnh, *xnl, *qh, *ql, *kh, *kl, *vh, *vl, *vth, *vtl, *ph, *pl, *hh, *hl;
    __nv_bfloat16 *wqh, *wql_, *wkh, *wkl, *wvh, *wvl, *f1h, *f1l, *f2h, *f2l;
    cudaGetSymbolAddress((void**)&xnh, g_xnh); cudaGetSymbolAddress((void**)&xnl, g_xnl);
    cudaGetSymbolAddress((void**)&qh,  g_qh);  cudaGetSymbolAddress((void**)&ql,  g_ql);
    cudaGetSymbolAddress((void**)&kh,  g_kh);  cudaGetSymbolAddress((void**)&kl,  g_kl);
    cudaGetSymbolAddress((void**)&vh,  g_vh);  cudaGetSymbolAddress((void**)&vl,  g_vl);
    cudaGetSymbolAddress((void**)&vth, g_vth); cudaGetSymbolAddress((void**)&vtl, g_vtl);
    cudaGetSymbolAddress((void**)&ph,  g_ph);  cudaGetSymbolAddress((void**)&pl,  g_pl);
    cudaGetSymbolAddress((void**)&hh,  g_hh);  cudaGetSymbolAddress((void**)&hl,  g_hl);
    cudaGetSymbolAddress((void**)&wqh, g_wqh); cudaGetSymbolAddress((void**)&wql_, g_wql);
    cudaGetSymbolAddress((void**)&wkh, g_wkh); cudaGetSymbolAddress((void**)&wkl, g_wkl);
    cudaGetSymbolAddress((void**)&wvh, g_wvh); cudaGetSymbolAddress((void**)&wvl, g_wvl);
    cudaGetSymbolAddress((void**)&f1h, g_f1h); cudaGetSymbolAddress((void**)&f1l, g_f1l);
    cudaGetSymbolAddress((void**)&f2h, g_f2h); cudaGetSymbolAddress((void**)&f2l, g_f2l);

    cudaFuncSetAttribute(tgemm<false, true,  false, false>, cudaFuncAttributeMaxDynamicSharedMemorySize, T_SMEM);
    cudaFuncSetAttribute(tgemm<true,  false, false, false>, cudaFuncAttributeMaxDynamicSharedMemorySize, T_SMEM);
    cudaFuncSetAttribute(tgemm<false, true,  true,  false>, cudaFuncAttributeMaxDynamicSharedMemorySize, T_SMEM);
    cudaFuncSetAttribute(tgemm<true,  false, false, true >, cudaFuncAttributeMaxDynamicSharedMemorySize, T_SMEM);

    const long long SD  = (long long)cS * cD;
    const long long SSq = (long long)cS * cS;
    const float inv_sqrt_d = 0.044194173824159216f; // 1/sqrt(512)

    enc_kernel<<<(cM * cD + 255) / 256, 256>>>(z, c, encw, encb, x);

    for (int l = 0; l < cL; l++) {
        cvt_kernel<<<(cD * cD + 255) / 256, 256>>>(wq + (long long)l * cD * cD, wqh, wql_, cD * cD);
        cvt_kernel<<<(cD * cD + 255) / 256, 256>>>(wk + (long long)l * cD * cD, wkh, wkl, cD * cD);
        cvt_kernel<<<(cD * cD + 255) / 256, 256>>>(wv + (long long)l * cD * cD, wvh, wvl, cD * cD);
        cvt_kernel<<<(cF * cD + 255) / 256, 256>>>(f1w + (long long)l * cF * cD, f1h, f1l, cF * cD);
        cvt_kernel<<<(cD * cF + 255) / 256, 256>>>(f2w + (long long)l * cD * cF, f2h, f2l, cD * cF);

        // pre-norm (ln1) -> hi/lo
        ln_kernel<<<cM, 128>>>(x, (const float*)0, ln1w + l * cD, ln1b + l * cD,
                               (float*)0, xnh, xnl);

        // QKV
        dim3 gQKV(cD / 128, cM / 128, 1);
        tgemm<false, true, false, false><<<gQKV, 256, T_SMEM>>>(
            xnh, xnl, wqh, wql_, bq + l * cD, (const float*)0,
            (float*)0, qh, ql, cD, cD, 0, 0, 0, 1.0f);
        tgemm<false, true, false, false><<<gQKV, 256, T_SMEM>>>(
            xnh, xnl, wkh, wkl, bk + l * cD, (const float*)0,
            (float*)0, kh, kl, cD, cD, 0, 0, 0, 1.0f);
        tgemm<false, true, false, false><<<gQKV, 256, T_SMEM>>>(
            xnh, xnl, wvh, wvl, bv + l * cD, (const float*)0,
            (float*)0, vh, vl, cD, cD, 0, 0, 0, 1.0f);

        // V transpose: [b,s,d] -> [b,d,s]
        tr_kernel<<<dim3(cD / 32, cS / 32, cB), 256>>>(vh, vl, vth, vtl);

        btab_kernel<<<cS / 256, 256>>>(beta, l, tab);

        // att = Q @ K^T / sqrt(d)
        dim3 gS(cS / 128, cS / 128, cB);
        tgemm<true, false, false, false><<<gS, 256, T_SMEM>>>(
            qh, ql, kh, kl, (const float*)0, (const float*)0,
            att, (__nv_bfloat16*)0, (__nv_bfloat16*)0, cS, cD, SD, SD, SSq, inv_sqrt_d);

        softmax_kernel<<<dim3(cS, cB), 256>>>(att, tab, ph, pl);

        // ao = P @ V  (B = V^T [d, s])
        dim3 gV(cD / 128, cS / 128, cB);
        tgemm<true, false, false, false><<<gV, 256, T_SMEM>>>(
            ph, pl, vth, vtl, (const float*)0, (const float*)0,
            ao, (__nv_bfloat16*)0, (__nv_bfloat16*)0, cD, cS, SSq, SD, SD, 1.0f);

        // x = LN(x + ao) with ln1
        ln_kernel<<<cM, 128>>>(x, ao, ln1w + l * cD, ln1b + l * cD, x,
                               (__nv_bfloat16*)0, (__nv_bfloat16*)0);
        // xn2 = LN(x) with ln2 -> hi/lo
        ln_kernel<<<cM, 128>>>(x, (const float*)0, ln2w + l * cD, ln2b + l * cD,
                               (float*)0, xnh, xnl);

        // h = relu(xn2 @ W1^T + b1)
        dim3 g1(cF / 128, cM / 128, 1);
        tgemm<false, true, true, false><<<g1, 256, T_SMEM>>>(
            xnh, xnl, f1h, f1l, f1b + l * cF, (const float*)0,
            (float*)0, hh, hl, cF, cD, 0, 0, 0, 1.0f);

        // x = x + h @ W2^T + b2
        dim3 g2(cD / 128, cM / 128, 1);
        tgemm<true, false, false, true><<<g2, 256, T_SMEM>>>(
            hh, hl, f2h, f2l, f2b + l * cD, x,
            x, (__nv_bfloat16*)0, (__nv_bfloat16*)0, cD, cF, 0, 0, 0, 1.0f);
    }

    out_kernel<<<cM / 8, 256>>>(x, ow, ob, (float*)d_out);
}

// round 10
// speedup vs baseline: 2.6276x; 1.0626x over previous
#include <cuda_runtime.h>
#include <cuda_bf16.h>
#include <stdint.h>
#include <math.h>

// Problem constants
static const int cB = 8;
static const int cS = 2048;
static const int cD = 512;
static const int cL = 6;
static const int cF = 2048;   // 4*D
static const int cM = cB * cS; // 16384 rows

// ---------------------------------------------------------------------------
// Scratch (static device allocations; no cudaMalloc allowed)
// ---------------------------------------------------------------------------
__device__ float g_x  [cM * cD];
__device__ float g_ao [cM * cD];
__device__ float g_att[(long long)cB * cS * cS];
__device__ float g_tab[cL * cS];

__device__ __nv_bfloat16 g_xnh[cM * cD], g_xnl[cM * cD];
__device__ __nv_bfloat16 g_qh [cM * cD], g_ql [cM * cD];
__device__ __nv_bfloat16 g_kh [cM * cD], g_kl [cM * cD];
__device__ __nv_bfloat16 g_vh [cM * cD], g_vl [cM * cD];
__device__ __nv_bfloat16 g_ph [(long long)cB * cS * cS], g_pl[(long long)cB * cS * cS];
__device__ __nv_bfloat16 g_hh [(long long)cM * cF],      g_hl[(long long)cM * cF];
// all-layer weight splits
__device__ __nv_bfloat16 g_wqh[cL * cD * cD], g_wql[cL * cD * cD];
__device__ __nv_bfloat16 g_wkh[cL * cD * cD], g_wkl[cL * cD * cD];
__device__ __nv_bfloat16 g_wvh[cL * cD * cD], g_wvl[cL * cD * cD];
__device__ __nv_bfloat16 g_f1h[cL * cF * cD], g_f1l[cL * cF * cD];
__device__ __nv_bfloat16 g_f2h[cL * cD * cF], g_f2l[cL * cD * cF];

// ---------------------------------------------------------------------------
// Portable PTX helpers (sm_80-level: mma.sync / ldmatrix / cp.async)
// ---------------------------------------------------------------------------
__device__ __forceinline__ uint32_t smem_to_u32(const void* p) {
    uint32_t a;
    asm("{ .reg .u64 t; cvta.to.shared.u64 t, %1; cvt.u32.u64 %0, t; }" : "=r"(a) : "l"(p));
    return a;
}
__device__ __forceinline__ void cp_async16(uint32_t saddr, const void* gaddr) {
    asm volatile("cp.async.cg.shared.global [%0], [%1], 16;" :: "r"(saddr), "l"(gaddr));
}
__device__ __forceinline__ void cp_commit() {
    asm volatile("cp.async.commit_group;");
}
template<int N>
__device__ __forceinline__ void cp_wait() {
    asm volatile("cp.async.wait_group %0;" :: "n"(N));
}
__device__ __forceinline__ void ldsm4(uint32_t* r, uint32_t addr) {
    asm volatile("ldmatrix.sync.aligned.m8n8.x4.shared.b16 {%0,%1,%2,%3}, [%4];"
        : "=r"(r[0]), "=r"(r[1]), "=r"(r[2]), "=r"(r[3]) : "r"(addr));
}
__device__ __forceinline__ void ldsm4t(uint32_t* r, uint32_t addr) {
    asm volatile("ldmatrix.sync.aligned.m8n8.x4.trans.shared.b16 {%0,%1,%2,%3}, [%4];"
        : "=r"(r[0]), "=r"(r[1]), "=r"(r[2]), "=r"(r[3]) : "r"(addr));
}
__device__ __forceinline__ void mma16816(float* c, const uint32_t* a, uint32_t b0, uint32_t b1) {
    asm volatile(
        "mma.sync.aligned.m16n8k16.row.col.f32.bf16.bf16.f32 "
        "{%0,%1,%2,%3}, {%4,%5,%6,%7}, {%8,%9}, {%0,%1,%2,%3};"
        : "+f"(c[0]), "+f"(c[1]), "+f"(c[2]), "+f"(c[3])
        : "r"(a[0]), "r"(a[1]), "r"(a[2]), "r"(a[3]), "r"(b0), "r"(b1));
}

// ---------------------------------------------------------------------------
// Encoder
// ---------------------------------------------------------------------------
__global__ void enc_kernel(const float* __restrict__ z, const float* __restrict__ c,
                           const float* __restrict__ ew, const float* __restrict__ eb,
                           float* __restrict__ x)
{
    long long idx = (long long)blockIdx.x * blockDim.x + threadIdx.x;
    if (idx >= (long long)cM * cD) return;
    int d = (int)(idx & (cD - 1));
    long long bs = idx >> 9;
    int s = (int)(bs & (cS - 1));
    const float factor = -1.7988946039015984e-2f;
    float div = expf((float)(2 * (d >> 1)) * factor);
    float ang = (float)s * div;
    float pe = (d & 1) ? cosf(ang) : sinf(ang);
    x[idx] = z[bs] * ew[2 * d] + c[bs] * ew[2 * d + 1] + eb[d] + pe;
}

// ---------------------------------------------------------------------------
// Bias tables for all layers: tab[l][t]
// ---------------------------------------------------------------------------
__global__ void btab_all(const float* __restrict__ beta, float* __restrict__ tab)
{
    int i = blockIdx.x * blockDim.x + threadIdx.x;
    if (i < cL * cS) {
        int l = i / cS, t = i - l * cS;
        const float TWO_PI = 6.283185307179586476925f;
        tab[i] = beta[2 * l] * cosf(TWO_PI * (float)t / 24.0f)
               + beta[2 * l + 1] * cosf(TWO_PI * (float)t / 720.0f);
    }
}

// ---------------------------------------------------------------------------
// Convert ALL weights (all layers) to hi/lo bf16 in one launch
// ---------------------------------------------------------------------------
__global__ void cvt_all(const float* wq, const float* wk, const float* wv,
                        const float* f1, const float* f2,
                        __nv_bfloat16* wqh, __nv_bfloat16* wql,
                        __nv_bfloat16* wkh, __nv_bfloat16* wkl,
                        __nv_bfloat16* wvh, __nv_bfloat16* wvl,
                        __nv_bfloat16* f1h, __nv_bfloat16* f1l,
                        __nv_bfloat16* f2h, __nv_bfloat16* f2l)
{
    const int nQ = cL * cD * cD;          // 1,572,864
    const int nF = cL * cF * cD;          // 6,291,456
    int i = blockIdx.x * blockDim.x + threadIdx.x;
    const float* src; __nv_bfloat16 *dh, *dl; int j;
    if (i < nQ)                    { src = wq; dh = wqh; dl = wql; j = i; }
    else if (i < 2 * nQ)           { src = wk; dh = wkh; dl = wkl; j = i - nQ; }
    else if (i < 3 * nQ)           { src = wv; dh = wvh; dl = wvl; j = i - 2 * nQ; }
    else if (i < 3 * nQ + nF)      { src = f1; dh = f1h; dl = f1l; j = i - 3 * nQ; }
    else if (i < 3 * nQ + 2 * nF)  { src = f2; dh = f2h; dl = f2l; j = i - 3 * nQ - nF; }
    else return;
    float v = src[j];
    __nv_bfloat16 hi = __float2bfloat16(v);
    dh[j] = hi;
    dl[j] = __float2bfloat16(v - __bfloat162float(hi));
}

// ---------------------------------------------------------------------------
// LayerNorm over D=512, optional fp32 out and/or hi/lo bf16 out
// ---------------------------------------------------------------------------
__global__ __launch_bounds__(128) void ln_kernel(
    const float* __restrict__ x, const float* __restrict__ res,
    const float* __restrict__ w, const float* __restrict__ b,
    float* __restrict__ out, __nv_bfloat16* __restrict__ oh, __nv_bfloat16* __restrict__ ol)
{
    long long off = (long long)blockIdx.x * cD + threadIdx.x * 4;
    float4 v = *(const float4*)(x + off);
    if (res) {
        float4 r = *(const float4*)(res + off);
        v.x += r.x; v.y += r.y; v.z += r.z; v.w += r.w;
    }
    int lane = threadIdx.x & 31, warp = threadIdx.x >> 5;
    __shared__ float red1[4];
    __shared__ float red2[4];

    float s = v.x + v.y + v.z + v.w;
    #pragma unroll
    for (int o = 16; o; o >>= 1) s += __shfl_xor_sync(0xffffffffu, s, o);
    if (lane == 0) red1[warp] = s;
    __syncthreads();
    float mean = (red1[0] + red1[1] + red1[2] + red1[3]) * (1.0f / 512.0f);

    float d0 = v.x - mean, d1 = v.y - mean, d2 = v.z - mean, d3 = v.w - mean;
    float q = d0 * d0 + d1 * d1 + d2 * d2 + d3 * d3;
    #pragma unroll
    for (int o = 16; o; o >>= 1) q += __shfl_xor_sync(0xffffffffu, q, o);
    if (lane == 0) red2[warp] = q;
    __syncthreads();
    float var = (red2[0] + red2[1] + red2[2] + red2[3]) * (1.0f / 512.0f);
    float rs = rsqrtf(var + 1e-5f);

    float4 wv = *(const float4*)(w + threadIdx.x * 4);
    float4 bv = *(const float4*)(b + threadIdx.x * 4);
    float o4[4];
    o4[0] = d0 * rs * wv.x + bv.x;
    o4[1] = d1 * rs * wv.y + bv.y;
    o4[2] = d2 * rs * wv.z + bv.z;
    o4[3] = d3 * rs * wv.w + bv.w;
    if (out) *(float4*)(out + off) = *(float4*)o4;
    if (oh) {
        __nv_bfloat16 hv[4], lv[4];
        #pragma unroll
        for (int i = 0; i < 4; i++) {
            hv[i] = __float2bfloat16(o4[i]);
            lv[i] = __float2bfloat16(o4[i] - __bfloat162float(hv[i]));
        }
        *(uint2*)(oh + off) = *(uint2*)hv;
        *(uint2*)(ol + off) = *(uint2*)lv;
    }
}

// ---------------------------------------------------------------------------
// Softmax with distance bias: fp32 logits in, hi/lo bf16 probs out
// ---------------------------------------------------------------------------
__global__ __launch_bounds__(256) void softmax_kernel(
    const float* __restrict__ att, const float* __restrict__ tab,
    __nv_bfloat16* __restrict__ ph, __nv_bfloat16* __restrict__ pl)
{
    __shared__ float buf[cS];
    __shared__ float red[8];
    int i = blockIdx.x, b = blockIdx.y;
    long long roff = ((long long)b * cS + i) * cS;
    const float* row = att + roff;
    int tid = threadIdx.x;

    float mx = -3.4e38f;
    for (int j = tid; j < cS; j += 256) {
        int d = i - j; if (d < 0) d = -d;
        float vv = row[j] + tab[d];
        buf[j] = vv;
        mx = fmaxf(mx, vv);
    }
    #pragma unroll
    for (int o = 16; o; o >>= 1) mx = fmaxf(mx, __shfl_xor_sync(0xffffffffu, mx, o));
    if ((tid & 31) == 0) red[tid >> 5] = mx;
    __syncthreads();
    float m = red[0];
    #pragma unroll
    for (int w2 = 1; w2 < 8; w2++) m = fmaxf(m, red[w2]);
    __syncthreads();

    float sum = 0.0f;
    for (int j = tid; j < cS; j += 256) {
        float e = expf(buf[j] - m);
        buf[j] = e;
        sum += e;
    }
    #pragma unroll
    for (int o = 16; o; o >>= 1) sum += __shfl_xor_sync(0xffffffffu, sum, o);
    if ((tid & 31) == 0) red[tid >> 5] = sum;
    __syncthreads();
    float tot = 0.0f;
    #pragma unroll
    for (int w2 = 0; w2 < 8; w2++) tot += red[w2];
    float inv = 1.0f / tot;
    for (int j = tid; j < cS; j += 256) {
        float p = buf[j] * inv;
        __nv_bfloat16 hv = __float2bfloat16(p);
        ph[roff + j] = hv;
        pl[roff + j] = __float2bfloat16(p - __bfloat162float(hv));
    }
}

// ---------------------------------------------------------------------------
// Tensor-core GEMM via mma.sync (bf16, 3-term hi/lo, fp32 accum):
//   C = alpha * (A @ opB) (+bias) (+src) (relu)
//   A: [M,K] bf16 hi/lo K-major.
//   BNN=false: B [N,K] K-major (opB = B^T), plain ldmatrix.
//   BNN=true:  B [K,N] row-major (opB = B),  ldmatrix.trans.
//   CTA tile 128x128x32, 8 warps (4m x 2n), warp tile 32x64, cp.async 2-stage.
// ---------------------------------------------------------------------------
static const int TPAD = 40;                       // TB k-stride (elems), 80B (16B-aligned, conflict-free)
static const int TPADN = 136;                     // NN n-stride (elems), 272B (16B-aligned; 272%128=16 -> conflict-free)
static const int TILE_BYTES = 128 * TPAD * 2;     // 10240 (NN B uses 32*272=8704 <= this)
static const int O_AH = 0;
static const int O_AL = O_AH + 2 * TILE_BYTES;
static const int O_BH = O_AL + 2 * TILE_BYTES;
static const int O_BL = O_BH + 2 * TILE_BYTES;
static const int T_SMEM = O_BL + 2 * TILE_BYTES;  // 81920 bytes

template<bool BNN, bool OUTF32, bool OUTHL, bool RELU, bool ADDSRC>
__global__ __launch_bounds__(256, 2) void tgemm(
    const __nv_bfloat16* __restrict__ Ah, const __nv_bfloat16* __restrict__ Al,
    const __nv_bfloat16* __restrict__ Bh, const __nv_bfloat16* __restrict__ Bl,
    const float* __restrict__ bias, const float* __restrict__ src,
    float* __restrict__ C, __nv_bfloat16* __restrict__ Ch, __nv_bfloat16* __restrict__ Cl,
    int N, int K, long long bsA, long long bsB, long long bsC, float alpha)
{
    extern __shared__ __align__(16) char smem[];
    const uint32_t sb = smem_to_u32(smem);
    const int tid = threadIdx.x;
    const int wid = tid >> 5, lane = tid & 31;

    Ah += (long long)blockIdx.z * bsA;  Al += (long long)blockIdx.z * bsA;
    Bh += (long long)blockIdx.z * bsB;  Bl += (long long)blockIdx.z * bsB;
    const long long zC = (long long)blockIdx.z * bsC;

    const int rowBase = blockIdx.y * 128;
    const int colBase = blockIdx.x * 128;

    // A loader: row = tid>>1 (0..127), off = (tid&1)*16 elems
    const int ldRow = tid >> 1;
    const int ldOff = (tid & 1) << 4;
    const long long gA = (long long)(rowBase + ldRow) * K + ldOff;
    const uint32_t sOffA = (uint32_t)(ldRow * TPAD + ldOff) * 2;

    // B loader (TB): same shape as A
    const long long gBt = (long long)(colBase + ldRow) * K + ldOff;
    // B loader (NN): tile 32(k) x 128(n); 2 chunks of 8 elems per thread per tensor
    const int nr0 = tid >> 4,         nc0 = tid & 15;
    const int nr1 = (tid + 256) >> 4, nc1 = tid & 15;
    const uint32_t sB0 = (uint32_t)(nr0 * TPADN + nc0 * 8) * 2;
    const uint32_t sB1 = (uint32_t)(nr1 * TPADN + nc1 * 8) * 2;
    const long long gBn0 = (long long)nr0 * N + colBase + nc0 * 8;
    const long long gBn1 = (long long)nr1 * N + colBase + nc1 * 8;

    const int nkt = K >> 5;

    // prologue: k-tile 0 -> buffer 0
    {
        cp_async16(sb + O_AH + sOffA,      Ah + gA);
        cp_async16(sb + O_AH + sOffA + 16, Ah + gA + 8);
        cp_async16(sb + O_AL + sOffA,      Al + gA);
        cp_async16(sb + O_AL + sOffA + 16, Al + gA + 8);
        if (BNN) {
            cp_async16(sb + O_BH + sB0, Bh + gBn0);
            cp_async16(sb + O_BH + sB1, Bh + gBn1);
            cp_async16(sb + O_BL + sB0, Bl + gBn0);
            cp_async16(sb + O_BL + sB1, Bl + gBn1);
        } else {
            cp_async16(sb + O_BH + sOffA,      Bh + gBt);
            cp_async16(sb + O_BH + sOffA + 16, Bh + gBt + 8);
            cp_async16(sb + O_BL + sOffA,      Bl + gBt);
            cp_async16(sb + O_BL + sOffA + 16, Bl + gBt + 8);
        }
        cp_commit();
    }

    // warp / lane geometry
    const int wm = wid >> 1;        // 0..3
    const int wn = wid & 1;         // 0..1
    const int lq = lane >> 3, lr = lane & 7;
    const int lrow = lr + (lq & 1) * 8;
    const int lcol = (lq >> 1) * 8;
    const uint32_t aBase  = (uint32_t)((wm * 32 + lrow) * TPAD + lcol) * 2;
    const uint32_t bBaseT = (uint32_t)((wn * 64 + lrow) * TPAD + lcol) * 2;
    // NN: address rows are k (lrow), byte col selects n within warp's 64
    const uint32_t bBaseN = (uint32_t)(lrow * TPADN + wn * 64 + lcol) * 2;

    float acc[16][4];
    #pragma unroll
    for (int i = 0; i < 16; i++)
        #pragma unroll
        for (int j = 0; j < 4; j++) acc[i][j] = 0.0f;

    for (int kt = 0; kt < nkt; kt++) {
        const int buf = kt & 1;
        if (kt + 1 < nkt) {
            const int nb = (kt + 1) & 1;
            const uint32_t bo = (uint32_t)nb * TILE_BYTES;
            const long long a0 = gA + (long long)(kt + 1) * 32;
            cp_async16(sb + O_AH + bo + sOffA,      Ah + a0);
            cp_async16(sb + O_AH + bo + sOffA + 16, Ah + a0 + 8);
            cp_async16(sb + O_AL + bo + sOffA,      Al + a0);
            cp_async16(sb + O_AL + bo + sOffA + 16, Al + a0 + 8);
            if (BNN) {
                const long long b0 = (long long)(kt + 1) * 32 * N;
                cp_async16(sb + O_BH + bo + sB0, Bh + b0 + gBn0);
                cp_async16(sb + O_BH + bo + sB1, Bh + b0 + gBn1);
                cp_async16(sb + O_BL + bo + sB0, Bl + b0 + gBn0);
                cp_async16(sb + O_BL + bo + sB1, Bl + b0 + gBn1);
            } else {
                const long long b0 = gBt + (long long)(kt + 1) * 32;
                cp_async16(sb + O_BH + bo + sOffA,      Bh + b0);
                cp_async16(sb + O_BH + bo + sOffA + 16, Bh + b0 + 8);
                cp_async16(sb + O_BL + bo + sOffA,      Bl + b0);
                cp_async16(sb + O_BL + bo + sOffA + 16, Bl + b0 + 8);
            }
            cp_commit();
            cp_wait<1>();
        } else {
            cp_wait<0>();
        }
        __syncthreads();

        const uint32_t ah0 = sb + O_AH + (uint32_t)buf * TILE_BYTES + aBase;
        const uint32_t al0 = sb + O_AL + (uint32_t)buf * TILE_BYTES + aBase;
        const uint32_t bh0 = sb + O_BH + (uint32_t)buf * TILE_BYTES + (BNN ? bBaseN : bBaseT);
        const uint32_t bl0 = sb + O_BL + (uint32_t)buf * TILE_BYTES + (BNN ? bBaseN : bBaseT);

        #pragma unroll
        for (int ks = 0; ks < 2; ks++) {
            uint32_t ah[2][4], al[2][4];
            ldsm4(ah[0], ah0 + ks * 32);
            ldsm4(ah[1], ah0 + 16 * TPAD * 2 + ks * 32);
            ldsm4(al[0], al0 + ks * 32);
            ldsm4(al[1], al0 + 16 * TPAD * 2 + ks * 32);
            #pragma unroll
            for (int np = 0; np < 4; np++) {
                uint32_t bh[4], bl[4];
                if (BNN) {
                    const uint32_t o = (uint32_t)(ks * 16 * TPADN * 2 + np * 32);
                    ldsm4t(bh, bh0 + o);
                    ldsm4t(bl, bl0 + o);
                } else {
                    const uint32_t o = (uint32_t)(np * 16 * TPAD * 2 + ks * 32);
                    ldsm4(bh, bh0 + o);
                    ldsm4(bl, bl0 + o);
                }
                // fragment selection: TB -> (bh[nt], bh[nt+2]); NN -> (bh[nt*2], bh[nt*2+1])
                #pragma unroll
                for (int mi = 0; mi < 2; mi++)
                    #pragma unroll
                    for (int nt = 0; nt < 2; nt++)
                        mma16816(acc[mi * 8 + np * 2 + nt], ah[mi],
                                 BNN ? bh[nt * 2] : bh[nt], BNN ? bh[nt * 2 + 1] : bh[nt + 2]);
                #pragma unroll
                for (int mi = 0; mi < 2; mi++)
                    #pragma unroll
                    for (int nt = 0; nt < 2; nt++)
                        mma16816(acc[mi * 8 + np * 2 + nt], ah[mi],
                                 BNN ? bl[nt * 2] : bl[nt], BNN ? bl[nt * 2 + 1] : bl[nt + 2]);
                #pragma unroll
                for (int mi = 0; mi < 2; mi++)
                    #pragma unroll
                    for (int nt = 0; nt < 2; nt++)
                        mma16816(acc[mi * 8 + np * 2 + nt], al[mi],
                                 BNN ? bh[nt * 2] : bh[nt], BNN ? bh[nt * 2 + 1] : bh[nt + 2]);
            }
        }
        __syncthreads();
    }

    // Epilogue
    const int eg = lane >> 2, et = (lane & 3) * 2;
    #pragma unroll
    for (int mi = 0; mi < 2; mi++) {
        #pragma unroll
        for (int np = 0; np < 4; np++) {
            #pragma unroll
            for (int nt = 0; nt < 2; nt++) {
                const float* cf = acc[mi * 8 + np * 2 + nt];
                const int col = colBase + wn * 64 + np * 16 + nt * 8 + et;
                #pragma unroll
                for (int hf = 0; hf < 2; hf++) {
                    const long long r = rowBase + wm * 32 + mi * 16 + eg + hf * 8;
                    float v0 = cf[hf * 2 + 0] * alpha;
                    float v1 = cf[hf * 2 + 1] * alpha;
                    if (bias) { v0 += bias[col]; v1 += bias[col + 1]; }
                    if (ADDSRC) {
                        float2 sv = *(const float2*)(src + zC + r * (long long)N + col);
                        v0 += sv.x; v1 += sv.y;
                    }
                    if (RELU) { v0 = fmaxf(v0, 0.0f); v1 = fmaxf(v1, 0.0f); }
                    if (OUTF32) {
                        float2 o; o.x = v0; o.y = v1;
                        *(float2*)(C + zC + r * (long long)N + col) = o;
                    }
                    if (OUTHL) {
                        __nv_bfloat16 h0 = __float2bfloat16(v0);
                        __nv_bfloat16 h1 = __float2bfloat16(v1);
                        __nv_bfloat16 l0 = __float2bfloat16(v0 - __bfloat162float(h0));
                        __nv_bfloat16 l1 = __float2bfloat16(v1 - __bfloat162float(h1));
                        __nv_bfloat16 hp[2] = {h0, h1};
                        __nv_bfloat16 lp[2] = {l0, l1};
                        *(uint32_t*)(Ch + zC + r * (long long)N + col) = *(uint32_t*)hp;
                        *(uint32_t*)(Cl + zC + r * (long long)N + col) = *(uint32_t*)lp;
                    }
                }
            }
        }
    }
}

// ---------------------------------------------------------------------------
// Output head (ODIM = 1)
// ---------------------------------------------------------------------------
__global__ __launch_bounds__(256) void out_kernel(
    const float* __restrict__ x, const float* __restrict__ ow,
    const float* __restrict__ ob, float* __restrict__ out)
{
    int warp = threadIdx.x >> 5, lane = threadIdx.x & 31;
    long long row = (long long)blockIdx.x * 8 + warp;
    const float* xr = x + row * cD;
    float s = 0.0f;
    #pragma unroll
    for (int j = lane; j < cD; j += 32) s += xr[j] * ow[j];
    #pragma unroll
    for (int o = 16; o; o >>= 1) s += __shfl_xor_sync(0xffffffffu, s, o);
    if (lane == 0) out[row] = s + ob[0];
}

// ---------------------------------------------------------------------------
// Launch
// ---------------------------------------------------------------------------
extern "C" void kernel_launch(void* const* d_in, const int* in_sizes, int n_in,
                              void* d_out, int out_size)
{
    (void)in_sizes; (void)n_in; (void)out_size;
    const float* z    = (const float*)d_in[0];
    const float* c    = (const float*)d_in[1];
    const float* encw = (const float*)d_in[2];
    const float* encb = (const float*)d_in[3];
    const float* beta = (const float*)d_in[4];
    const float* wq   = (const float*)d_in[5];
    const float* bq   = (const float*)d_in[6];
    const float* wk   = (const float*)d_in[7];
    const float* bk   = (const float*)d_in[8];
    const float* wv   = (const float*)d_in[9];
    const float* bv   = (const float*)d_in[10];
    const float* ln1w = (const float*)d_in[11];
    const float* ln1b = (const float*)d_in[12];
    const float* ln2w = (const float*)d_in[13];
    const float* ln2b = (const float*)d_in[14];
    const float* f1w  = (const float*)d_in[15];
    const float* f1b  = (const float*)d_in[16];
    const float* f2w  = (const float*)d_in[17];
    const float* f2b  = (const float*)d_in[18];
    const float* ow   = (const float*)d_in[19];
    const float* ob   = (const float*)d_in[20];

    float *x, *ao, *att, *tab;
    cudaGetSymbolAddress((void**)&x,   g_x);
    cudaGetSymbolAddress((void**)&ao,  g_ao);
    cudaGetSymbolAddress((void**)&att, g_att);
    cudaGetSymbolAddress((void**)&tab, g_tab);
    __nv_bfloat16 *xnh, *xnl, *qh, *ql, *kh, *kl, *vh, *vl, *ph, *pl, *hh, *hl;
    __nv_bfloat16 *wqh, *wql_, *wkh, *wkl, *wvh, *wvl, *f1h, *f1l, *f2h, *f2l;
    cudaGetSymbolAddress((void**)&xnh, g_xnh); cudaGetSymbolAddress((void**)&xnl, g_xnl);
    cudaGetSymbolAddress((void**)&qh,  g_qh);  cudaGetSymbolAddress((void**)&ql,  g_ql);
    cudaGetSymbolAddress((void**)&kh,  g_kh);  cudaGetSymbolAddress((void**)&kl,  g_kl);
    cudaGetSymbolAddress((void**)&vh,  g_vh);  cudaGetSymbolAddress((void**)&vl,  g_vl);
    cudaGetSymbolAddress((void**)&ph,  g_ph);  cudaGetSymbolAddress((void**)&pl,  g_pl);
    cudaGetSymbolAddress((void**)&hh,  g_hh);  cudaGetSymbolAddress((void**)&hl,  g_hl);
    cudaGetSymbolAddress((void**)&wqh, g_wqh); cudaGetSymbolAddress((void**)&wql_, g_wql);
    cudaGetSymbolAddress((void**)&wkh, g_wkh); cudaGetSymbolAddress((void**)&wkl, g_wkl);
    cudaGetSymbolAddress((void**)&wvh, g_wvh); cudaGetSymbolAddress((void**)&wvl, g_wvl);
    cudaGetSymbolAddress((void**)&f1h, g_f1h); cudaGetSymbolAddress((void**)&f1l, g_f1l);
    cudaGetSymbolAddress((void**)&f2h, g_f2h); cudaGetSymbolAddress((void**)&f2l, g_f2l);

    cudaFuncSetAttribute(tgemm<false, false, true,  false, false>, cudaFuncAttributeMaxDynamicSharedMemorySize, T_SMEM);
    cudaFuncSetAttribute(tgemm<false, true,  false, false, false>, cudaFuncAttributeMaxDynamicSharedMemorySize, T_SMEM);
    cudaFuncSetAttribute(tgemm<true,  true,  false, false, false>, cudaFuncAttributeMaxDynamicSharedMemorySize, T_SMEM);
    cudaFuncSetAttribute(tgemm<false, false, true,  true,  false>, cudaFuncAttributeMaxDynamicSharedMemorySize, T_SMEM);
    cudaFuncSetAttribute(tgemm<false, true,  false, false, true >, cudaFuncAttributeMaxDynamicSharedMemorySize, T_SMEM);

    const long long SD  = (long long)cS * cD;
    const long long SSq = (long long)cS * cS;
    const float inv_sqrt_d = 0.044194173824159216f; // 1/sqrt(512)

    enc_kernel<<<(cM * cD + 255) / 256, 256>>>(z, c, encw, encb, x);          // launch 0
    btab_all<<<(cL * cS + 255) / 256, 256>>>(beta, tab);                      // launch 1
    {
        const int total = 3 * cL * cD * cD + 2 * cL * cF * cD;
        cvt_all<<<(total + 255) / 256, 256>>>(wq, wk, wv, f1w, f2w,           // launch 2
                                              wqh, wql_, wkh, wkl, wvh, wvl,
                                              f1h, f1l, f2h, f2l);
    }

    for (int l = 0; l < cL; l++) {
        const long long oQ = (long long)l * cD * cD;
        const long long oF1 = (long long)l * cF * cD;
        const long long oF2 = (long long)l * cD * cF;

        // pre-norm (ln1) -> hi/lo
        ln_kernel<<<cM, 128>>>(x, (const float*)0, ln1w + l * cD, ln1b + l * cD,
                               (float*)0, xnh, xnl);

        // QKV
        dim3 gQKV(cD / 128, cM / 128, 1);
        tgemm<false, false, true, false, false><<<gQKV, 256, T_SMEM>>>(
            xnh, xnl, wqh + oQ, wql_ + oQ, bq + l * cD, (const float*)0,
            (float*)0, qh, ql, cD, cD, 0, 0, 0, 1.0f);
        tgemm<false, false, true, false, false><<<gQKV, 256, T_SMEM>>>(
            xnh, xnl, wkh + oQ, wkl + oQ, bk + l * cD, (const float*)0,
            (float*)0, kh, kl, cD, cD, 0, 0, 0, 1.0f);
        tgemm<false, false, true, false, false><<<gQKV, 256, T_SMEM>>>(
            xnh, xnl, wvh + oQ, wvl + oQ, bv + l * cD, (const float*)0,
            (float*)0, vh, vl, cD, cD, 0, 0, 0, 1.0f);

        // att = Q @ K^T / sqrt(d)
        dim3 gS(cS / 128, cS / 128, cB);
        tgemm<false, true, false, false, false><<<gS, 256, T_SMEM>>>(
            qh, ql, kh, kl, (const float*)0, (const float*)0,
            att, (__nv_bfloat16*)0, (__nv_bfloat16*)0, cS, cD, SD, SD, SSq, inv_sqrt_d);

        softmax_kernel<<<dim3(cS, cB), 256>>>(att, tab + l * cS, ph, pl);

        // ao = P @ V (NN: B = V [s, d] row-major, trans-ldmatrix)
        dim3 gV(cD / 128, cS / 128, cB);
        tgemm<true, true, false, false, false><<<gV, 256, T_SMEM>>>(
            ph, pl, vh, vl, (const float*)0, (const float*)0,
            ao, (__nv_bfloat16*)0, (__nv_bfloat16*)0, cD, cS, SSq, SD, SD, 1.0f);

        // x = LN(x + ao) with ln1
        ln_kernel<<<cM, 128>>>(x, ao, ln1w + l * cD, ln1b + l * cD, x,
                               (__nv_bfloat16*)0, (__nv_bfloat16*)0);
        // xn2 = LN(x) with ln2 -> hi/lo
        ln_kernel<<<cM, 128>>>(x, (const float*)0, ln2w + l * cD, ln2b + l * cD,
                               (float*)0, xnh, xnl);

        // h = relu(xn2 @ W1^T + b1)
        dim3 g1(cF / 128, cM / 128, 1);
        tgemm<false, false, true, true, false><<<g1, 256, T_SMEM>>>(
            xnh, xnl, f1h + oF1, f1l + oF1, f1b + l * cF, (const float*)0,
            (float*)0, hh, hl, cF, cD, 0, 0, 0, 1.0f);

        // x = x + h @ W2^T + b2
        dim3 g2(cD / 128, cM / 128, 1);
        tgemm<false, true, false, false, true><<<g2, 256, T_SMEM>>>(
            hh, hl, f2h + oF2, f2l + oF2, f2b + l * cD, x,
            x, (__nv_bfloat16*)0, (__nv_bfloat16*)0, cD, cF, 0, 0, 0, 1.0f);
    }

    out_kernel<<<cM / 8, 256>>>(x, ow, ob, (float*)d_out);
}